// round 6
// baseline (speedup 1.0000x reference)
#include <cuda_runtime.h>
#include <math.h>
#include <stdint.h>

#define B_ 32
#define T_ 128

typedef unsigned long long u64t;

// Scratch (device globals: allocation-free)
__device__ float d_M[4 * 4096];                 // S0, 2S0^2-I, S1, 2S1^2-I
__device__ float d_out0[B_ * T_ * 4096];        // layer-0 h states
__device__ float d_last[B_ * 4096];             // layer-1 h at last relevant t
__device__ float d_Gx[(size_t)B_ * T_ * 64 * 128]; // gate x-part preactivations (+bias)
__device__ float d_Cx[(size_t)B_ * T_ * 64 * 64];  // cand x-part preactivations (+bias)

// ---------------- f32x2 helpers ----------------
__device__ __forceinline__ u64t pack_dup(float x) {
    u64t r; asm("mov.b64 %0, {%1,%1};" : "=l"(r) : "f"(x)); return r;
}
__device__ __forceinline__ u64t pack2(float lo, float hi) {
    u64t r; asm("mov.b64 %0, {%1,%2};" : "=l"(r) : "f"(lo), "f"(hi)); return r;
}
__device__ __forceinline__ float2 unpack2(u64t v) {
    float2 f; asm("mov.b64 {%0,%1}, %2;" : "=f"(f.x), "=f"(f.y) : "l"(v)); return f;
}
__device__ __forceinline__ void fma2(u64t& d, u64t a, u64t b) {
    asm("fma.rn.f32x2 %0, %1, %2, %0;" : "+l"(d) : "l"(a), "l"(b));
}

__device__ __forceinline__ uint32_t s_u32(const void* p) {
    return (uint32_t)__cvta_generic_to_shared(p);
}
__device__ __forceinline__ uint32_t mapa_rank(uint32_t a, uint32_t r) {
    uint32_t o;
    asm("mapa.shared::cluster.u32 %0, %1, %2;" : "=r"(o) : "r"(a), "r"(r));
    return o;
}
__device__ __forceinline__ float ldc_f32(uint32_t a) {
    float v;
    asm volatile("ld.shared::cluster.f32 %0, [%1];" : "=f"(v) : "r"(a));
    return v;
}
#define CLUSTER_SYNC() do { \
    asm volatile("barrier.cluster.arrive.aligned;" ::: "memory"); \
    asm volatile("barrier.cluster.wait.aligned;"   ::: "memory"); } while (0)

extern __shared__ float smem[];

// ---------------------------------------------------------------------------
// Precompute diffusion operators.
// ---------------------------------------------------------------------------
__global__ void prep_kernel(const float* __restrict__ S0, const float* __restrict__ S1)
{
    __shared__ float Ss[64 * 64];
    const int s = blockIdx.x;
    const float* S = s ? S1 : S0;
    for (int i = threadIdx.x; i < 4096; i += blockDim.x) Ss[i] = S[i];
    __syncthreads();
    for (int i = threadIdx.x; i < 4096; i += blockDim.x) {
        int m = i >> 6, n = i & 63;
        float acc = 0.f;
        #pragma unroll 8
        for (int p = 0; p < 64; ++p) acc += Ss[m * 64 + p] * Ss[p * 64 + n];
        d_M[(2 * s) * 4096 + i]     = Ss[i];
        d_M[(2 * s + 1) * 4096 + i] = 2.f * acc - (m == n ? 1.f : 0.f);
    }
}

// ---------------------------------------------------------------------------
// Precompute x-contributions for every (b,t).
// Key change vs R5: A operands (x, xa_k) stored TRANSPOSED [feat][node] with
// pitch 66 -> lane-consecutive scalar LDS, conflict-free, 1 wavefront/load
// (the old lane-varying LDS.128 at 272B stride touched 8 lines per phase).
// M for phase 1 stored [in][out] pitch 66 for the same reason.
// smem: x_row 64x68 | x_T 64x66 | xa_T 4x64x66 | M_T 4x64x66
// ---------------------------------------------------------------------------
#define PRE_SMEM_BYTES ((4352 + 4224 + 4 * 4224 + 4 * 4224) * 4)

__global__ void __launch_bounds__(512, 1)
pre_kernel(const float* __restrict__ Xin,
           const float* __restrict__ Wg, const float* __restrict__ bg,
           const float* __restrict__ Wc, const float* __restrict__ bc,
           int layer)
{
    float* x_row = smem;                     // 64*68  [node][feat] (uniform vec reads)
    float* x_T   = smem + 4352;              // 64*66  [feat][node]
    float* xa_T  = smem + 4352 + 4224;       // 4 * 64*66 [feat][node]
    float* M_T   = smem + 4352 + 4224 * 5;   // 4 * 64*66 [in][out]

    const int tid = threadIdx.x;
    const int bt  = blockIdx.x;
    const int r0  = tid & 31;                // node rows {r0, r0+32}
    const int g   = tid >> 5;                // warp id 0..15 (uniform)

    const float* xsrc = (layer ? d_out0 : Xin) + (size_t)bt * 4096;

    for (int i = tid; i < 4096; i += 512) {
        int n = i >> 6, d = i & 63;
        float v = xsrc[i];
        x_row[n * 68 + d] = v;
        x_T[d * 66 + n]   = v;
    }
    for (int i = tid; i < 16384; i += 512) {
        int k = i >> 12, r = (i >> 6) & 63, c = i & 63;   // d_M[k][r=out][c=in]
        M_T[k * 4224 + c * 66 + r] = d_M[i];
    }
    __syncthreads();

    // ---------------- phase 1: xa_k = M_k @ x (output transposed) ----------------
    // thread: out rows {r0, r0+32}, feature cols [g*4, g*4+4)
    {
        const int c4 = g * 4;
        #pragma unroll
        for (int k = 0; k < 4; ++k) {
            const float* MT = M_T + k * 4224;
            u64t a00 = 0, a01 = 0, a10 = 0, a11 = 0;
            #pragma unroll 4
            for (int p = 0; p < 64; ++p) {
                float m0 = MT[p * 66 + r0];
                float m1 = MT[p * 66 + r0 + 32];
                ulonglong2 xv = *(const ulonglong2*)(x_row + p * 68 + c4); // uniform
                u64t d0 = pack_dup(m0);
                u64t d1 = pack_dup(m1);
                fma2(a00, d0, xv.x); fma2(a01, d0, xv.y);
                fma2(a10, d1, xv.x); fma2(a11, d1, xv.y);
            }
            float* XT = xa_T + k * 4224;
            float2 v00 = unpack2(a00), v01 = unpack2(a01);
            float2 v10 = unpack2(a10), v11 = unpack2(a11);
            XT[(c4 + 0) * 66 + r0] = v00.x;
            XT[(c4 + 1) * 66 + r0] = v00.y;
            XT[(c4 + 2) * 66 + r0] = v01.x;
            XT[(c4 + 3) * 66 + r0] = v01.y;
            XT[(c4 + 0) * 66 + r0 + 32] = v10.x;
            XT[(c4 + 1) * 66 + r0 + 32] = v10.y;
            XT[(c4 + 2) * 66 + r0 + 32] = v11.x;
            XT[(c4 + 3) * 66 + r0 + 32] = v11.y;
        }
    }
    __syncthreads();

    // ---------------- phase 2: Gx / Cx (merged, A scalar conflict-free) ----------
    {
        const int gb = g * 8;
        const int cb = g * 4;
        u64t ag0[4], ag1[4], ac0[2], ac1[2];
        #pragma unroll
        for (int q = 0; q < 4; ++q) {
            u64t bb = pack2(bg[gb + 2 * q], bg[gb + 2 * q + 1]);
            ag0[q] = bb; ag1[q] = bb;
        }
        ac0[0] = ac1[0] = pack2(bc[cb], bc[cb + 1]);
        ac0[1] = ac1[1] = pack2(bc[cb + 2], bc[cb + 3]);

        for (int k = 0; k < 5; ++k) {
            const float* AT = (k == 0) ? x_T : (xa_T + (k - 1) * 4224);
            const float* WgK = Wg + (size_t)(k * 128) * 128 + gb;
            const float* WcK = Wc + (size_t)(k * 128) * 64 + cb;
            #pragma unroll 4
            for (int p = 0; p < 64; ++p) {
                float a0 = AT[p * 66 + r0];        // 1 wf
                float a1 = AT[p * 66 + r0 + 32];   // 1 wf
                ulonglong2 w0 = *(const ulonglong2*)(WgK + (size_t)p * 128);
                ulonglong2 w1 = *(const ulonglong2*)(WgK + (size_t)p * 128 + 4);
                ulonglong2 wc = *(const ulonglong2*)(WcK + (size_t)p * 64);
                u64t d0 = pack_dup(a0);
                u64t d1 = pack_dup(a1);
                fma2(ag0[0], d0, w0.x); fma2(ag0[1], d0, w0.y);
                fma2(ag0[2], d0, w1.x); fma2(ag0[3], d0, w1.y);
                fma2(ag1[0], d1, w0.x); fma2(ag1[1], d1, w0.y);
                fma2(ag1[2], d1, w1.x); fma2(ag1[3], d1, w1.y);
                fma2(ac0[0], d0, wc.x); fma2(ac0[1], d0, wc.y);
                fma2(ac1[0], d1, wc.x); fma2(ac1[1], d1, wc.y);
            }
        }

        float* gx = d_Gx + (size_t)bt * 8192;
        float* cx = d_Cx + (size_t)bt * 4096;
        ulonglong2 s;
        s.x = ag0[0]; s.y = ag0[1]; *(ulonglong2*)(gx + r0 * 128 + gb) = s;
        s.x = ag0[2]; s.y = ag0[3]; *(ulonglong2*)(gx + r0 * 128 + gb + 4) = s;
        s.x = ag1[0]; s.y = ag1[1]; *(ulonglong2*)(gx + (r0 + 32) * 128 + gb) = s;
        s.x = ag1[2]; s.y = ag1[3]; *(ulonglong2*)(gx + (r0 + 32) * 128 + gb + 4) = s;
        s.x = ac0[0]; s.y = ac0[1]; *(ulonglong2*)(cx + r0 * 64 + cb) = s;
        s.x = ac1[0]; s.y = ac1[1]; *(ulonglong2*)(cx + (r0 + 32) * 64 + cb) = s;
    }
}

// ---------------------------------------------------------------------------
// Persistent per-layer scan (h-half only). Grid 128 = 32 batches x cluster(4).
// v3: 512 threads (4 warps/SMSP) — each thread owns ONE row in every phase,
// halving per-thread work and doubling latency-hiding warps.
// ---------------------------------------------------------------------------
#define SCAN_SMEM_BYTES (55872 * 4)

__global__ void __launch_bounds__(512, 1) __cluster_dims__(4, 1, 1)
scan_kernel(const float* __restrict__ Wg, const float* __restrict__ Wc,
            const int* __restrict__ lens, int layer)
{
    float* wg_h = smem;
    float* wc_h = smem + 10240;
    float* Ms   = smem + 15360;
    float* h_s  = smem + 32768;
    float* rh_s = smem + 36928;
    float* V_s  = smem + 41088;
    float* rst  = smem + 52608;
    float* ugs  = smem + 53696;
    float* hst  = smem + 54784;

    const int tid = threadIdx.x;
    const int b = blockIdx.x >> 2;
    const int j = blockIdx.x & 3;

    // one-time loads
    for (int i = tid; i < 10240; i += 512) {           // wg_h[k][d][c] = Wg[k*128+64+d][gmap]
        int k = i >> 11, d = (i >> 5) & 63, c = i & 31;
        int g = (c < 16) ? (j * 16 + c) : (64 + j * 16 + (c - 16));
        wg_h[i] = Wg[(size_t)(k * 128 + 64 + d) * 128 + g];
    }
    for (int i = tid; i < 5120; i += 512) {            // wc_h[k][d][c]
        int k = i >> 10, d = (i >> 4) & 63, c = i & 15;
        wc_h[i] = Wc[(size_t)(k * 128 + 64 + d) * 64 + j * 16 + c];
    }
    for (int i = tid; i < 16384; i += 512) {
        int k = i >> 12, r = (i >> 6) & 63, p = i & 63;
        Ms[k * 4352 + r * 68 + p] = d_M[i];
    }
    for (int i = tid; i < 4096; i += 512)
        h_s[(i >> 6) * 65 + (i & 63)] = 0.f;

    int idx_t = lens[b] - 1;
    idx_t = idx_t < 0 ? 0 : (idx_t > T_ - 1 ? T_ - 1 : idx_t);

    uint32_t rbase[4], hbase[4];
    #pragma unroll
    for (int r = 0; r < 4; ++r) {
        rbase[r] = mapa_rank(s_u32(rst), (uint32_t)r);
        hbase[r] = mapa_rank(s_u32(hst), (uint32_t)r);
    }

    const int lane = tid & 31;
    const int w    = tid >> 5;                // 16 warps
    const int vrow = (w & 1) * 32 + lane;     // V-phase row (0..63)
    const int jg   = w >> 1;                  // V-phase col group (0..7)
    const int mg   = tid >> 3;                // M-apply row (0..63)
    const int ja4  = (tid & 7) * 4;           // gate M-apply cols
    const int ja2  = (tid & 7) * 2;           // cand M-apply cols
    const int g0   = (ja4 < 16) ? (j * 16 + ja4) : (64 + j * 16 + (ja4 - 16));
    const int c0   = j * 16 + ja2;

    const float* gxb = d_Gx + (size_t)b * T_ * 8192;
    const float* cxb = d_Cx + (size_t)b * T_ * 4096;

    for (int t = 0; t < T_; ++t) {
        __syncthreads();

        const float* gx = gxb + (size_t)t * 8192;
        const float* cx = cxb + (size_t)t * 4096;
        float4 gA = __ldg((const float4*)(gx + mg * 128 + g0));
        float2 cA = __ldg((const float2*)(cx + mg * 64 + c0));

        // ---------- gate V-phase: V_k = h @ wg_h[k], all 5 k ----------
        {
            u64t acc[5][2];
            #pragma unroll
            for (int k = 0; k < 5; ++k) { acc[k][0] = acc[k][1] = 0; }
            const float* hp = h_s + vrow * 65;
            const float* wbase = wg_h + jg * 4;
            #pragma unroll 4
            for (int d = 0; d < 64; ++d) {
                u64t a = pack_dup(hp[d]);
                #pragma unroll
                for (int k = 0; k < 5; ++k) {
                    ulonglong2 wv = *(const ulonglong2*)(wbase + k * 2048 + d * 32);
                    fma2(acc[k][0], a, wv.x); fma2(acc[k][1], a, wv.y);
                }
            }
            #pragma unroll
            for (int k = 0; k < 5; ++k) {
                ulonglong2 s;
                s.x = acc[k][0]; s.y = acc[k][1];
                *(ulonglong2*)(V_s + k * 2304 + vrow * 36 + jg * 4) = s;
            }
        }
        __syncthreads();

        // ---------- gate M-apply + sigmoid + stage (one row per thread) ----------
        {
            float4 vA = *(const float4*)(V_s + mg * 36 + ja4);
            u64t y0 = pack2(gA.x + vA.x, gA.y + vA.y);
            u64t y1 = pack2(gA.z + vA.z, gA.w + vA.w);
            for (int k = 1; k < 5; ++k) {
                const float* Mk = Ms + (k - 1) * 4352;
                const float* Vk = V_s + k * 2304;
                #pragma unroll 4
                for (int m = 0; m < 64; m += 4) {
                    float4 mA = *(const float4*)(Mk + mg * 68 + m);
                    float mAa[4] = {mA.x, mA.y, mA.z, mA.w};
                    #pragma unroll
                    for (int q = 0; q < 4; ++q) {
                        ulonglong2 v = *(const ulonglong2*)(Vk + (m + q) * 36 + ja4);
                        u64t dm = pack_dup(mAa[q]);
                        fma2(y0, dm, v.x); fma2(y1, dm, v.y);
                    }
                }
            }
            float2 p0 = unpack2(y0), p1 = unpack2(y1);
            float va[4] = {p0.x, p0.y, p1.x, p1.y};
            #pragma unroll
            for (int q = 0; q < 4; ++q) {
                int c = ja4 + q;
                float s0 = 1.f / (1.f + expf(-va[q]));
                if (c < 16) rst[mg * 17 + c] = s0;
                else        ugs[mg * 17 + c - 16] = s0;
            }
        }

        CLUSTER_SYNC();   // r stages visible cluster-wide

        // rh = r * h (r gathered via DSMEM)
        #pragma unroll 2
        for (int i = tid; i < 4096; i += 512) {
            int n = i >> 6, d = i & 63;
            float r = ldc_f32(rbase[d >> 4] + (uint32_t)(n * 17 + (d & 15)) * 4);
            rh_s[n * 65 + d] = r * h_s[n * 65 + d];
        }
        __syncthreads();

        // ---------- cand V-phase ----------
        {
            u64t acc[5];
            #pragma unroll
            for (int k = 0; k < 5; ++k) acc[k] = 0;
            const float* hp = rh_s + vrow * 65;
            const float* wbase = wc_h + jg * 2;
            #pragma unroll 4
            for (int d = 0; d < 64; ++d) {
                u64t a = pack_dup(hp[d]);
                #pragma unroll
                for (int k = 0; k < 5; ++k) {
                    u64t wv = *(const u64t*)(wbase + k * 1024 + d * 16);
                    fma2(acc[k], a, wv);
                }
            }
            #pragma unroll
            for (int k = 0; k < 5; ++k)
                *(u64t*)(V_s + k * 2304 + vrow * 36 + jg * 2) = acc[k];
        }
        __syncthreads();

        // ---------- cand M-apply + GRU update (one row per thread) ----------
        {
            float2 v0 = *(const float2*)(V_s + mg * 36 + ja2);
            u64t y = pack2(cA.x + v0.x, cA.y + v0.y);
            for (int k = 1; k < 5; ++k) {
                const float* Mk = Ms + (k - 1) * 4352;
                const float* Vk = V_s + k * 2304;
                #pragma unroll 4
                for (int m = 0; m < 64; m += 4) {
                    float4 mA = *(const float4*)(Mk + mg * 68 + m);
                    float mAa[4] = {mA.x, mA.y, mA.z, mA.w};
                    #pragma unroll
                    for (int q = 0; q < 4; ++q) {
                        u64t v = *(const u64t*)(Vk + (m + q) * 36 + ja2);
                        fma2(y, pack_dup(mAa[q]), v);
                    }
                }
            }
            float* hout0 = d_out0 + ((size_t)(b * T_ + t)) * 4096;
            float2 cc = unpack2(y);
            float cand[2] = {cc.x, cc.y};
            #pragma unroll
            for (int q = 0; q < 2; ++q) {
                int cl = ja2 + q;
                int col = j * 16 + cl;
                float cv = tanhf(cand[q]);
                float ug = ugs[mg * 17 + cl];
                float hn = ug * h_s[mg * 65 + col] + (1.f - ug) * cv;
                hst[mg * 17 + cl] = hn;
                if (layer == 0)      hout0[mg * 64 + col] = hn;
                else if (t == idx_t) d_last[(size_t)b * 4096 + mg * 64 + col] = hn;
            }
        }

        CLUSTER_SYNC();   // h stages visible cluster-wide

        // assemble full h for next step
        #pragma unroll 2
        for (int i = tid; i < 4096; i += 512) {
            int n = i >> 6, d = i & 63;
            h_s[n * 65 + d] = ldc_f32(hbase[d >> 4] + (uint32_t)(n * 17 + (d & 15)) * 4);
        }
    }
    CLUSTER_SYNC();   // no CTA exits while peers may still read its DSMEM
}

// ---------------------------------------------------------------------------
// Final projection + node max-pool
// ---------------------------------------------------------------------------
__global__ void final_kernel(const float* __restrict__ Wp, const float* __restrict__ bp,
                             float* __restrict__ out)
{
    __shared__ float red[64 * 4];
    const int b = blockIdx.x, n = threadIdx.x;
    const float* h = d_last + (size_t)b * 4096 + n * 64;
    float l0 = bp[0], l1 = bp[1], l2 = bp[2], l3 = bp[3];
    #pragma unroll 8
    for (int d = 0; d < 64; ++d) {
        float v = fmaxf(h[d], 0.f);
        l0 += v * Wp[d * 4 + 0];
        l1 += v * Wp[d * 4 + 1];
        l2 += v * Wp[d * 4 + 2];
        l3 += v * Wp[d * 4 + 3];
    }
    red[n * 4 + 0] = l0; red[n * 4 + 1] = l1; red[n * 4 + 2] = l2; red[n * 4 + 3] = l3;
    __syncthreads();
    for (int s = 32; s > 0; s >>= 1) {
        if (n < s) {
            #pragma unroll
            for (int c = 0; c < 4; ++c)
                red[n * 4 + c] = fmaxf(red[n * 4 + c], red[(n + s) * 4 + c]);
        }
        __syncthreads();
    }
    if (n < 4) out[b * 4 + n] = red[n];
}

// ---------------------------------------------------------------------------
extern "C" void kernel_launch(void* const* d_in, const int* in_sizes, int n_in,
                              void* d_out, int out_size)
{
    (void)in_sizes; (void)n_in; (void)out_size;
    const float* X   = (const float*)d_in[0];
    const int*   len = (const int*)  d_in[1];
    const float* S0  = (const float*)d_in[2];
    const float* S1  = (const float*)d_in[3];
    const float* Wg0 = (const float*)d_in[4];
    const float* bg0 = (const float*)d_in[5];
    const float* Wc0 = (const float*)d_in[6];
    const float* bc0 = (const float*)d_in[7];
    const float* Wg1 = (const float*)d_in[8];
    const float* bg1 = (const float*)d_in[9];
    const float* Wc1 = (const float*)d_in[10];
    const float* bc1 = (const float*)d_in[11];
    const float* Wp  = (const float*)d_in[12];
    const float* bp  = (const float*)d_in[13];
    float* out = (float*)d_out;

    cudaFuncSetAttribute(pre_kernel,  cudaFuncAttributeMaxDynamicSharedMemorySize, PRE_SMEM_BYTES);
    cudaFuncSetAttribute(scan_kernel, cudaFuncAttributeMaxDynamicSharedMemorySize, SCAN_SMEM_BYTES);

    prep_kernel<<<2, 256>>>(S0, S1);
    pre_kernel<<<B_ * T_, 512, PRE_SMEM_BYTES>>>(X, Wg0, bg0, Wc0, bc0, 0);
    scan_kernel<<<128, 512, SCAN_SMEM_BYTES>>>(Wg0, Wc0, len, 0);
    pre_kernel<<<B_ * T_, 512, PRE_SMEM_BYTES>>>(X, Wg1, bg1, Wc1, bc1, 1);
    scan_kernel<<<128, 512, SCAN_SMEM_BYTES>>>(Wg1, Wc1, len, 1);
    final_kernel<<<B_, 64>>>(Wp, bp, out);
}

// round 7
// speedup vs baseline: 1.2330x; 1.2330x over previous
#include <cuda_runtime.h>
#include <math.h>
#include <stdint.h>

#define B_ 32
#define T_ 128

typedef unsigned long long u64t;

// Scratch (device globals: allocation-free)
__device__ float d_M[4 * 4096];                 // S0, 2S0^2-I, S1, 2S1^2-I
__device__ float d_out0[B_ * T_ * 4096];        // layer-0 h states
__device__ float d_last[B_ * 4096];             // layer-1 h at last relevant t
__device__ float d_Gx[(size_t)B_ * T_ * 64 * 128]; // gate x-part preactivations (+bias)
__device__ float d_Cx[(size_t)B_ * T_ * 64 * 64];  // cand x-part preactivations (+bias)

// ---------------- f32x2 helpers ----------------
__device__ __forceinline__ u64t pack_dup(float x) {
    u64t r; asm("mov.b64 %0, {%1,%1};" : "=l"(r) : "f"(x)); return r;
}
__device__ __forceinline__ u64t pack2(float lo, float hi) {
    u64t r; asm("mov.b64 %0, {%1,%2};" : "=l"(r) : "f"(lo), "f"(hi)); return r;
}
__device__ __forceinline__ float2 unpack2(u64t v) {
    float2 f; asm("mov.b64 {%0,%1}, %2;" : "=f"(f.x), "=f"(f.y) : "l"(v)); return f;
}
__device__ __forceinline__ void fma2(u64t& d, u64t a, u64t b) {
    asm("fma.rn.f32x2 %0, %1, %2, %0;" : "+l"(d) : "l"(a), "l"(b));
}

__device__ __forceinline__ uint32_t s_u32(const void* p) {
    return (uint32_t)__cvta_generic_to_shared(p);
}
__device__ __forceinline__ uint32_t mapa_rank(uint32_t a, uint32_t r) {
    uint32_t o;
    asm("mapa.shared::cluster.u32 %0, %1, %2;" : "=r"(o) : "r"(a), "r"(r));
    return o;
}
__device__ __forceinline__ float ldc_f32(uint32_t a) {
    float v;
    asm volatile("ld.shared::cluster.f32 %0, [%1];" : "=f"(v) : "r"(a));
    return v;
}
__device__ __forceinline__ void cp16(float* dst, const float* src) {
    asm volatile("cp.async.cg.shared.global [%0], [%1], 16;"
                 :: "r"(s_u32(dst)), "l"(src));
}
#define CP_COMMIT() asm volatile("cp.async.commit_group;")
#define CP_WAIT1()  asm volatile("cp.async.wait_group 1;")
#define CLUSTER_SYNC() do { \
    asm volatile("barrier.cluster.arrive.aligned;" ::: "memory"); \
    asm volatile("barrier.cluster.wait.aligned;"   ::: "memory"); } while (0)

// fast activations (bounded preactivations; __expf/__fdividef err ~1e-6 rel)
__device__ __forceinline__ float sigmoid_f(float v) {
    return __fdividef(1.f, 1.f + __expf(-v));
}
__device__ __forceinline__ float tanh_f(float v) {
    return 1.f - __fdividef(2.f, __expf(2.f * v) + 1.f);
}

extern __shared__ float smem[];

// ---------------------------------------------------------------------------
// Precompute diffusion operators.
// ---------------------------------------------------------------------------
__global__ void prep_kernel(const float* __restrict__ S0, const float* __restrict__ S1)
{
    __shared__ float Ss[64 * 64];
    const int s = blockIdx.x;
    const float* S = s ? S1 : S0;
    for (int i = threadIdx.x; i < 4096; i += blockDim.x) Ss[i] = S[i];
    __syncthreads();
    for (int i = threadIdx.x; i < 4096; i += blockDim.x) {
        int m = i >> 6, n = i & 63;
        float acc = 0.f;
        #pragma unroll 8
        for (int p = 0; p < 64; ++p) acc += Ss[m * 64 + p] * Ss[p * 64 + n];
        d_M[(2 * s) * 4096 + i]     = Ss[i];
        d_M[(2 * s + 1) * 4096 + i] = 2.f * acc - (m == n ? 1.f : 0.f);
    }
}

// ---------------------------------------------------------------------------
// Precompute x-contributions for every (b,t). v3:
//  - 24 output cols per warp (16 gate + 8 cand) -> load:fma ratio halved
//  - W_k staged in SMEM via double-buffered cp.async (shares the region M_T
//    occupies during phase 1) -> W reads are broadcast LDS, no LDG stream
// smem (floats): x_row 0(4352) | x_T 4352(4224) | xa_T 8576(16896)
//                shared 25472(24576): phase1 M_T / phase2 wbuf[2][12288]
// ---------------------------------------------------------------------------
#define PRE_SMEM_FLOATS 50048
#define PRE_SMEM_BYTES (PRE_SMEM_FLOATS * 4)

__global__ void __launch_bounds__(512, 1)
pre_kernel(const float* __restrict__ Xin,
           const float* __restrict__ Wg, const float* __restrict__ bg,
           const float* __restrict__ Wc, const float* __restrict__ bc,
           int layer)
{
    float* x_row = smem;             // [node][feat] pitch 68 (uniform vec reads)
    float* x_T   = smem + 4352;      // [feat][node] pitch 66
    float* xa_T  = smem + 8576;      // 4 x [feat][node] pitch 66
    float* M_T   = smem + 25472;     // phase1: 4 x [in][out] pitch 66
    float* wbuf  = smem + 25472;     // phase2: 2 x 12288 (gate[p][128], cand @8192 [p][64])

    const int tid  = threadIdx.x;
    const int bt   = blockIdx.x;
    const int lane = tid & 31;
    const int g    = tid >> 5;           // warp 0..15

    const float* xsrc = (layer ? d_out0 : Xin) + (size_t)bt * 4096;

    for (int i = tid; i < 4096; i += 512) {
        int n = i >> 6, d = i & 63;
        float v = xsrc[i];
        x_row[n * 68 + d] = v;
        x_T[d * 66 + n]   = v;
    }
    for (int i = tid; i < 16384; i += 512) {
        int k = i >> 12, r = (i >> 6) & 63, c = i & 63;   // d_M[k][out=r][in=c]
        M_T[k * 4224 + c * 66 + r] = d_M[i];
    }
    __syncthreads();

    // ---------------- phase 1: xa_k = M_k @ x (stored transposed) ----------------
    // warp g: feature cols c4 = g*4; lane: out-rows {lane, lane+32}
    {
        const int c4 = g * 4;
        #pragma unroll
        for (int k = 0; k < 4; ++k) {
            const float* MT = M_T + k * 4224;
            u64t a00 = 0, a01 = 0, a10 = 0, a11 = 0;
            #pragma unroll 4
            for (int p = 0; p < 64; ++p) {
                u64t d0 = pack_dup(MT[p * 66 + lane]);
                u64t d1 = pack_dup(MT[p * 66 + lane + 32]);
                ulonglong2 xv = *(const ulonglong2*)(x_row + p * 68 + c4); // uniform
                fma2(a00, d0, xv.x); fma2(a01, d0, xv.y);
                fma2(a10, d1, xv.x); fma2(a11, d1, xv.y);
            }
            float* XT = xa_T + k * 4224;
            float2 v00 = unpack2(a00), v01 = unpack2(a01);
            float2 v10 = unpack2(a10), v11 = unpack2(a11);
            XT[(c4 + 0) * 66 + lane] = v00.x;
            XT[(c4 + 1) * 66 + lane] = v00.y;
            XT[(c4 + 2) * 66 + lane] = v01.x;
            XT[(c4 + 3) * 66 + lane] = v01.y;
            XT[(c4 + 0) * 66 + lane + 32] = v10.x;
            XT[(c4 + 1) * 66 + lane + 32] = v10.y;
            XT[(c4 + 2) * 66 + lane + 32] = v11.x;
            XT[(c4 + 3) * 66 + lane + 32] = v11.y;
        }
    }
    __syncthreads();   // M_T reads done -> wbuf may overwrite

    // ---------------- phase 2: Gx / Cx with cp.async'd W ----------------
    // warp g: colgroup cg = g&7 (gate 16 cols, cand 8 cols), rowhalf rh = g>>3
    const int cg = g & 7;
    const int row = (g >> 3) * 32 + lane;   // 0..63
    const int gb = cg * 16;
    const int cb = cg * 8;

    // prefetch k=0 W into buf 0
    {
        float* wb = wbuf;
        const float* wgk = Wg;   // rows 0..63 (k=0 x-part), 128 cols, contiguous
        const float* wck = Wc;
        for (int i = tid; i < 2048; i += 512) cp16(wb + i * 4, wgk + i * 4);
        for (int i = tid; i < 1024; i += 512) cp16(wb + 8192 + i * 4, wck + i * 4);
        CP_COMMIT();
    }

    u64t ag[8], ac[4];
    #pragma unroll
    for (int q = 0; q < 8; ++q) ag[q] = pack2(bg[gb + 2 * q], bg[gb + 2 * q + 1]);
    #pragma unroll
    for (int q = 0; q < 4; ++q) ac[q] = pack2(bc[cb + 2 * q], bc[cb + 2 * q + 1]);

    #pragma unroll
    for (int k = 0; k < 5; ++k) {
        // prefetch k+1 (or empty group to keep wait_group constant)
        if (k < 4) {
            float* wb = wbuf + ((k + 1) & 1) * 12288;
            const float* wgk = Wg + (size_t)((k + 1) * 128) * 128;
            const float* wck = Wc + (size_t)((k + 1) * 128) * 64;
            for (int i = tid; i < 2048; i += 512) cp16(wb + i * 4, wgk + i * 4);
            for (int i = tid; i < 1024; i += 512) cp16(wb + 8192 + i * 4, wck + i * 4);
        }
        CP_COMMIT();
        CP_WAIT1();        // buffer k ready (k+1 group may stay in flight)
        __syncthreads();

        const float* AT = (k == 0) ? x_T : (xa_T + (k - 1) * 4224);
        const float* wgb = wbuf + (k & 1) * 12288 + gb;
        const float* wcb = wbuf + (k & 1) * 12288 + 8192 + cb;

        #pragma unroll 4
        for (int p = 0; p < 64; ++p) {
            u64t a = pack_dup(AT[p * 66 + row]);           // 1 wf scalar LDS
            ulonglong2 w0 = *(const ulonglong2*)(wgb + p * 128);      // uniform
            ulonglong2 w1 = *(const ulonglong2*)(wgb + p * 128 + 4);
            ulonglong2 w2 = *(const ulonglong2*)(wgb + p * 128 + 8);
            ulonglong2 w3 = *(const ulonglong2*)(wgb + p * 128 + 12);
            ulonglong2 wc4 = *(const ulonglong2*)(wcb + p * 64);
            ulonglong2 wc5 = *(const ulonglong2*)(wcb + p * 64 + 4);
            fma2(ag[0], a, w0.x); fma2(ag[1], a, w0.y);
            fma2(ag[2], a, w1.x); fma2(ag[3], a, w1.y);
            fma2(ag[4], a, w2.x); fma2(ag[5], a, w2.y);
            fma2(ag[6], a, w3.x); fma2(ag[7], a, w3.y);
            fma2(ac[0], a, wc4.x); fma2(ac[1], a, wc4.y);
            fma2(ac[2], a, wc5.x); fma2(ac[3], a, wc5.y);
        }
        __syncthreads();   // all reads of buf[k&1] done before iter k+1 overwrites buf[(k+2)&1]... guards reuse
    }

    float* gx = d_Gx + (size_t)bt * 8192 + row * 128 + gb;
    float* cx = d_Cx + (size_t)bt * 4096 + row * 64 + cb;
    ulonglong2 s;
    s.x = ag[0]; s.y = ag[1]; *(ulonglong2*)(gx)      = s;
    s.x = ag[2]; s.y = ag[3]; *(ulonglong2*)(gx + 4)  = s;
    s.x = ag[4]; s.y = ag[5]; *(ulonglong2*)(gx + 8)  = s;
    s.x = ag[6]; s.y = ag[7]; *(ulonglong2*)(gx + 12) = s;
    s.x = ac[0]; s.y = ac[1]; *(ulonglong2*)(cx)      = s;
    s.x = ac[2]; s.y = ac[3]; *(ulonglong2*)(cx + 4)  = s;
}

// ---------------------------------------------------------------------------
// Persistent per-layer scan (h-half only). Grid 128 = 32 batches x cluster(4).
// R5 256-thread version (proven) + fast activations.
// ---------------------------------------------------------------------------
#define SCAN_SMEM_BYTES (55872 * 4)

__global__ void __launch_bounds__(256, 1) __cluster_dims__(4, 1, 1)
scan_kernel(const float* __restrict__ Wg, const float* __restrict__ Wc,
            const int* __restrict__ lens, int layer)
{
    float* wg_h = smem;
    float* wc_h = smem + 10240;
    float* Ms   = smem + 15360;
    float* h_s  = smem + 32768;
    float* rh_s = smem + 36928;
    float* V_s  = smem + 41088;
    float* rst  = smem + 52608;
    float* ugs  = smem + 53696;
    float* hst  = smem + 54784;

    const int tid = threadIdx.x;
    const int b = blockIdx.x >> 2;
    const int j = blockIdx.x & 3;

    // one-time loads
    for (int i = tid; i < 10240; i += 256) {           // wg_h[k][d][c] = Wg[k*128+64+d][gmap]
        int k = i >> 11, d = (i >> 5) & 63, c = i & 31;
        int g = (c < 16) ? (j * 16 + c) : (64 + j * 16 + (c - 16));
        wg_h[i] = Wg[(size_t)(k * 128 + 64 + d) * 128 + g];
    }
    for (int i = tid; i < 5120; i += 256) {            // wc_h[k][d][c]
        int k = i >> 10, d = (i >> 4) & 63, c = i & 15;
        wc_h[i] = Wc[(size_t)(k * 128 + 64 + d) * 64 + j * 16 + c];
    }
    for (int i = tid; i < 16384; i += 256) {
        int k = i >> 12, r = (i >> 6) & 63, p = i & 63;
        Ms[k * 4352 + r * 68 + p] = d_M[i];
    }
    for (int i = tid; i < 4096; i += 256)
        h_s[(i >> 6) * 65 + (i & 63)] = 0.f;

    int idx_t = lens[b] - 1;
    idx_t = idx_t < 0 ? 0 : (idx_t > T_ - 1 ? T_ - 1 : idx_t);

    uint32_t rbase[4], hbase[4];
    #pragma unroll
    for (int r = 0; r < 4; ++r) {
        rbase[r] = mapa_rank(s_u32(rst), (uint32_t)r);
        hbase[r] = mapa_rank(s_u32(hst), (uint32_t)r);
    }

    const int rg  = tid & 31;
    const int jg  = tid >> 5;
    const int mg  = tid >> 3;
    const int ja4 = (tid & 7) * 4;
    const int ja2 = (tid & 7) * 2;
    const int g0  = (ja4 < 16) ? (j * 16 + ja4) : (64 + j * 16 + (ja4 - 16));
    const int c0  = j * 16 + ja2;

    const float* gxb = d_Gx + (size_t)b * T_ * 8192;
    const float* cxb = d_Cx + (size_t)b * T_ * 4096;

    for (int t = 0; t < T_; ++t) {
        __syncthreads();

        const float* gx = gxb + (size_t)t * 8192;
        const float* cx = cxb + (size_t)t * 4096;
        float4 gA = __ldg((const float4*)(gx + mg * 128 + g0));
        float4 gB = __ldg((const float4*)(gx + (mg + 32) * 128 + g0));
        float2 cA = __ldg((const float2*)(cx + mg * 64 + c0));
        float2 cB = __ldg((const float2*)(cx + (mg + 32) * 64 + c0));

        // ---------- gate V-phase: V_k = h @ wg_h[k], all 5 k ----------
        {
            u64t acc[5][4];
            #pragma unroll
            for (int k = 0; k < 5; ++k) { acc[k][0] = acc[k][1] = acc[k][2] = acc[k][3] = 0; }
            const float* h0p = h_s + rg * 65;
            const float* h1p = h_s + (rg + 32) * 65;
            const float* wbase = wg_h + jg * 4;
            #pragma unroll 4
            for (int d = 0; d < 64; ++d) {
                u64t a0 = pack_dup(h0p[d]);
                u64t a1 = pack_dup(h1p[d]);
                #pragma unroll
                for (int k = 0; k < 5; ++k) {
                    ulonglong2 w = *(const ulonglong2*)(wbase + k * 2048 + d * 32);
                    fma2(acc[k][0], a0, w.x); fma2(acc[k][1], a0, w.y);
                    fma2(acc[k][2], a1, w.x); fma2(acc[k][3], a1, w.y);
                }
            }
            #pragma unroll
            for (int k = 0; k < 5; ++k) {
                ulonglong2 s;
                s.x = acc[k][0]; s.y = acc[k][1];
                *(ulonglong2*)(V_s + k * 2304 + rg * 36 + jg * 4) = s;
                s.x = acc[k][2]; s.y = acc[k][3];
                *(ulonglong2*)(V_s + k * 2304 + (rg + 32) * 36 + jg * 4) = s;
            }
        }
        __syncthreads();

        // ---------- gate M-apply + sigmoid + stage ----------
        {
            float4 vA = *(const float4*)(V_s + mg * 36 + ja4);
            float4 vB = *(const float4*)(V_s + (mg + 32) * 36 + ja4);
            u64t y00 = pack2(gA.x + vA.x, gA.y + vA.y);
            u64t y01 = pack2(gA.z + vA.z, gA.w + vA.w);
            u64t y10 = pack2(gB.x + vB.x, gB.y + vB.y);
            u64t y11 = pack2(gB.z + vB.z, gB.w + vB.w);
            for (int k = 1; k < 5; ++k) {
                const float* Mk = Ms + (k - 1) * 4352;
                const float* Vk = V_s + k * 2304;
                #pragma unroll 4
                for (int m = 0; m < 64; m += 4) {
                    float4 mA = *(const float4*)(Mk + mg * 68 + m);
                    float4 mB = *(const float4*)(Mk + (mg + 32) * 68 + m);
                    float mAa[4] = {mA.x, mA.y, mA.z, mA.w};
                    float mBa[4] = {mB.x, mB.y, mB.z, mB.w};
                    #pragma unroll
                    for (int q = 0; q < 4; ++q) {
                        ulonglong2 v = *(const ulonglong2*)(Vk + (m + q) * 36 + ja4);
                        u64t da = pack_dup(mAa[q]);
                        u64t db = pack_dup(mBa[q]);
                        fma2(y00, da, v.x); fma2(y01, da, v.y);
                        fma2(y10, db, v.x); fma2(y11, db, v.y);
                    }
                }
            }
            float2 p00 = unpack2(y00), p01 = unpack2(y01);
            float2 p10 = unpack2(y10), p11 = unpack2(y11);
            float v0a[4] = {p00.x, p00.y, p01.x, p01.y};
            float v1a[4] = {p10.x, p10.y, p11.x, p11.y};
            #pragma unroll
            for (int q = 0; q < 4; ++q) {
                int c = ja4 + q;
                float s0 = sigmoid_f(v0a[q]);
                float s1 = sigmoid_f(v1a[q]);
                if (c < 16) { rst[mg * 17 + c] = s0;        rst[(mg + 32) * 17 + c] = s1; }
                else        { ugs[mg * 17 + c - 16] = s0;   ugs[(mg + 32) * 17 + c - 16] = s1; }
            }
        }

        CLUSTER_SYNC();   // r stages visible cluster-wide

        // rh = r * h (r gathered via DSMEM)
        #pragma unroll 4
        for (int i = tid; i < 4096; i += 256) {
            int n = i >> 6, d = i & 63;
            float r = ldc_f32(rbase[d >> 4] + (uint32_t)(n * 17 + (d & 15)) * 4);
            rh_s[n * 65 + d] = r * h_s[n * 65 + d];
        }
        __syncthreads();

        // ---------- cand V-phase ----------
        {
            u64t acc[5][2];
            #pragma unroll
            for (int k = 0; k < 5; ++k) { acc[k][0] = acc[k][1] = 0; }
            const float* h0p = rh_s + rg * 65;
            const float* h1p = rh_s + (rg + 32) * 65;
            const float* wbase = wc_h + jg * 2;
            #pragma unroll 4
            for (int d = 0; d < 64; ++d) {
                u64t a0 = pack_dup(h0p[d]);
                u64t a1 = pack_dup(h1p[d]);
                #pragma unroll
                for (int k = 0; k < 5; ++k) {
                    u64t w = *(const u64t*)(wbase + k * 1024 + d * 16);
                    fma2(acc[k][0], a0, w);
                    fma2(acc[k][1], a1, w);
                }
            }
            #pragma unroll
            for (int k = 0; k < 5; ++k) {
                *(u64t*)(V_s + k * 2304 + rg * 36 + jg * 2)        = acc[k][0];
                *(u64t*)(V_s + k * 2304 + (rg + 32) * 36 + jg * 2) = acc[k][1];
            }
        }
        __syncthreads();

        // ---------- cand M-apply + GRU update ----------
        {
            float2 v0 = *(const float2*)(V_s + mg * 36 + ja2);
            float2 v1 = *(const float2*)(V_s + (mg + 32) * 36 + ja2);
            u64t y0 = pack2(cA.x + v0.x, cA.y + v0.y);
            u64t y1 = pack2(cB.x + v1.x, cB.y + v1.y);
            for (int k = 1; k < 5; ++k) {
                const float* Mk = Ms + (k - 1) * 4352;
                const float* Vk = V_s + k * 2304;
                #pragma unroll 4
                for (int m = 0; m < 64; m += 4) {
                    float4 mA = *(const float4*)(Mk + mg * 68 + m);
                    float4 mB = *(const float4*)(Mk + (mg + 32) * 68 + m);
                    float mAa[4] = {mA.x, mA.y, mA.z, mA.w};
                    float mBa[4] = {mB.x, mB.y, mB.z, mB.w};
                    #pragma unroll
                    for (int q = 0; q < 4; ++q) {
                        u64t v = *(const u64t*)(Vk + (m + q) * 36 + ja2);
                        fma2(y0, pack_dup(mAa[q]), v);
                        fma2(y1, pack_dup(mBa[q]), v);
                    }
                }
            }
            float* hout0 = d_out0 + ((size_t)(b * T_ + t)) * 4096;
            float2 cc0 = unpack2(y0), cc1 = unpack2(y1);
            float cand0[2] = {cc0.x, cc0.y};
            float cand1[2] = {cc1.x, cc1.y};
            #pragma unroll
            for (int q = 0; q < 2; ++q) {
                int cl = ja2 + q;
                int col = j * 16 + cl;
                float cv0 = tanh_f(cand0[q]);
                float ug0 = ugs[mg * 17 + cl];
                float hn0 = ug0 * h_s[mg * 65 + col] + (1.f - ug0) * cv0;
                hst[mg * 17 + cl] = hn0;
                float cv1 = tanh_f(cand1[q]);
                float ug1 = ugs[(mg + 32) * 17 + cl];
                float hn1 = ug1 * h_s[(mg + 32) * 65 + col] + (1.f - ug1) * cv1;
                hst[(mg + 32) * 17 + cl] = hn1;
                if (layer == 0) {
                    hout0[mg * 64 + col]        = hn0;
                    hout0[(mg + 32) * 64 + col] = hn1;
                } else if (t == idx_t) {
                    d_last[(size_t)b * 4096 + mg * 64 + col]        = hn0;
                    d_last[(size_t)b * 4096 + (mg + 32) * 64 + col] = hn1;
                }
            }
        }

        CLUSTER_SYNC();   // h stages visible cluster-wide

        // assemble full h for next step
        #pragma unroll 4
        for (int i = tid; i < 4096; i += 256) {
            int n = i >> 6, d = i & 63;
            h_s[n * 65 + d] = ldc_f32(hbase[d >> 4] + (uint32_t)(n * 17 + (d & 15)) * 4);
        }
    }
    CLUSTER_SYNC();   // no CTA exits while peers may still read its DSMEM
}

// ---------------------------------------------------------------------------
// Final projection + node max-pool
// ---------------------------------------------------------------------------
__global__ void final_kernel(const float* __restrict__ Wp, const float* __restrict__ bp,
                             float* __restrict__ out)
{
    __shared__ float red[64 * 4];
    const int b = blockIdx.x, n = threadIdx.x;
    const float* h = d_last + (size_t)b * 4096 + n * 64;
    float l0 = bp[0], l1 = bp[1], l2 = bp[2], l3 = bp[3];
    #pragma unroll 8
    for (int d = 0; d < 64; ++d) {
        float v = fmaxf(h[d], 0.f);
        l0 += v * Wp[d * 4 + 0];
        l1 += v * Wp[d * 4 + 1];
        l2 += v * Wp[d * 4 + 2];
        l3 += v * Wp[d * 4 + 3];
    }
    red[n * 4 + 0] = l0; red[n * 4 + 1] = l1; red[n * 4 + 2] = l2; red[n * 4 + 3] = l3;
    __syncthreads();
    for (int s = 32; s > 0; s >>= 1) {
        if (n < s) {
            #pragma unroll
            for (int c = 0; c < 4; ++c)
                red[n * 4 + c] = fmaxf(red[n * 4 + c], red[(n + s) * 4 + c]);
        }
        __syncthreads();
    }
    if (n < 4) out[b * 4 + n] = red[n];
}

// ---------------------------------------------------------------------------
extern "C" void kernel_launch(void* const* d_in, const int* in_sizes, int n_in,
                              void* d_out, int out_size)
{
    (void)in_sizes; (void)n_in; (void)out_size;
    const float* X   = (const float*)d_in[0];
    const int*   len = (const int*)  d_in[1];
    const float* S0  = (const float*)d_in[2];
    const float* S1  = (const float*)d_in[3];
    const float* Wg0 = (const float*)d_in[4];
    const float* bg0 = (const float*)d_in[5];
    const float* Wc0 = (const float*)d_in[6];
    const float* bc0 = (const float*)d_in[7];
    const float* Wg1 = (const float*)d_in[8];
    const float* bg1 = (const float*)d_in[9];
    const float* Wc1 = (const float*)d_in[10];
    const float* bc1 = (const float*)d_in[11];
    const float* Wp  = (const float*)d_in[12];
    const float* bp  = (const float*)d_in[13];
    float* out = (float*)d_out;

    cudaFuncSetAttribute(pre_kernel,  cudaFuncAttributeMaxDynamicSharedMemorySize, PRE_SMEM_BYTES);
    cudaFuncSetAttribute(scan_kernel, cudaFuncAttributeMaxDynamicSharedMemorySize, SCAN_SMEM_BYTES);

    prep_kernel<<<2, 256>>>(S0, S1);
    pre_kernel<<<B_ * T_, 512, PRE_SMEM_BYTES>>>(X, Wg0, bg0, Wc0, bc0, 0);
    scan_kernel<<<128, 256, SCAN_SMEM_BYTES>>>(Wg0, Wc0, len, 0);
    pre_kernel<<<B_ * T_, 512, PRE_SMEM_BYTES>>>(X, Wg1, bg1, Wc1, bc1, 1);
    scan_kernel<<<128, 256, SCAN_SMEM_BYTES>>>(Wg1, Wc1, len, 1);
    final_kernel<<<B_, 64>>>(Wp, bp, out);
}

// round 8
// speedup vs baseline: 1.2968x; 1.0518x over previous
#include <cuda_runtime.h>
#include <math.h>
#include <stdint.h>

#define B_ 32
#define T_ 128

typedef unsigned long long u64t;

// Scratch (device globals: allocation-free)
__device__ float d_M[4 * 4096];                 // S0, 2S0^2-I, S1, 2S1^2-I
__device__ float d_out0[B_ * T_ * 4096];        // layer-0 h states
__device__ float d_last[B_ * 4096];             // layer-1 h at last relevant t
__device__ float d_Gx[(size_t)B_ * T_ * 64 * 128]; // gate x-part preactivations (+bias)
__device__ float d_Cx[(size_t)B_ * T_ * 64 * 64];  // cand x-part preactivations (+bias)

// ---------------- f32x2 helpers ----------------
__device__ __forceinline__ u64t pack_dup(float x) {
    u64t r; asm("mov.b64 %0, {%1,%1};" : "=l"(r) : "f"(x)); return r;
}
__device__ __forceinline__ u64t pack2(float lo, float hi) {
    u64t r; asm("mov.b64 %0, {%1,%2};" : "=l"(r) : "f"(lo), "f"(hi)); return r;
}
__device__ __forceinline__ float2 unpack2(u64t v) {
    float2 f; asm("mov.b64 {%0,%1}, %2;" : "=f"(f.x), "=f"(f.y) : "l"(v)); return f;
}
__device__ __forceinline__ void fma2(u64t& d, u64t a, u64t b) {
    asm("fma.rn.f32x2 %0, %1, %2, %0;" : "+l"(d) : "l"(a), "l"(b));
}

__device__ __forceinline__ uint32_t s_u32(const void* p) {
    return (uint32_t)__cvta_generic_to_shared(p);
}
__device__ __forceinline__ uint32_t mapa_rank(uint32_t a, uint32_t r) {
    uint32_t o;
    asm("mapa.shared::cluster.u32 %0, %1, %2;" : "=r"(o) : "r"(a), "r"(r));
    return o;
}
__device__ __forceinline__ float ldc_f32(uint32_t a) {
    float v;
    asm volatile("ld.shared::cluster.f32 %0, [%1];" : "=f"(v) : "r"(a));
    return v;
}
__device__ __forceinline__ void cp16(float* dst, const float* src) {
    asm volatile("cp.async.cg.shared.global [%0], [%1], 16;"
                 :: "r"(s_u32(dst)), "l"(src));
}
#define CP_COMMIT() asm volatile("cp.async.commit_group;")
#define CP_WAIT1()  asm volatile("cp.async.wait_group 1;")
#define CLUSTER_ARRIVE() asm volatile("barrier.cluster.arrive.aligned;" ::: "memory")
#define CLUSTER_WAIT()   asm volatile("barrier.cluster.wait.aligned;"   ::: "memory")
#define CLUSTER_SYNC() do { CLUSTER_ARRIVE(); CLUSTER_WAIT(); } while (0)

// fast activations (bounded preactivations; __expf/__fdividef err ~1e-6 rel)
__device__ __forceinline__ float sigmoid_f(float v) {
    return __fdividef(1.f, 1.f + __expf(-v));
}
__device__ __forceinline__ float tanh_f(float v) {
    return 1.f - __fdividef(2.f, __expf(2.f * v) + 1.f);
}

extern __shared__ float smem[];

// ---------------------------------------------------------------------------
// Precompute diffusion operators.
// ---------------------------------------------------------------------------
__global__ void prep_kernel(const float* __restrict__ S0, const float* __restrict__ S1)
{
    __shared__ float Ss[64 * 64];
    const int s = blockIdx.x;
    const float* S = s ? S1 : S0;
    for (int i = threadIdx.x; i < 4096; i += blockDim.x) Ss[i] = S[i];
    __syncthreads();
    for (int i = threadIdx.x; i < 4096; i += blockDim.x) {
        int m = i >> 6, n = i & 63;
        float acc = 0.f;
        #pragma unroll 8
        for (int p = 0; p < 64; ++p) acc += Ss[m * 64 + p] * Ss[p * 64 + n];
        d_M[(2 * s) * 4096 + i]     = Ss[i];
        d_M[(2 * s + 1) * 4096 + i] = 2.f * acc - (m == n ? 1.f : 0.f);
    }
}

// ---------------------------------------------------------------------------
// Precompute x-contributions for every (b,t). v4:
//  - tile reshape: 2 rows x 12 cols per thread (8 gate + 4 cand per warp,
//    rows lane/lane+32) -> 5 LDS per p vs 12 fma2 (was 7:12) -> fma-bound
//  - W_k double-buffered in SMEM via cp.async (unchanged from v3)
// smem (floats): x_row 0(4352) | x_T 4352(4224) | xa_T 8576(16896)
//                shared 25472(24576): phase1 M_T / phase2 wbuf[2][12288]
// ---------------------------------------------------------------------------
#define PRE_SMEM_FLOATS 50048
#define PRE_SMEM_BYTES (PRE_SMEM_FLOATS * 4)

__global__ void __launch_bounds__(512, 1)
pre_kernel(const float* __restrict__ Xin,
           const float* __restrict__ Wg, const float* __restrict__ bg,
           const float* __restrict__ Wc, const float* __restrict__ bc,
           int layer)
{
    float* x_row = smem;             // [node][feat] pitch 68 (uniform vec reads)
    float* x_T   = smem + 4352;      // [feat][node] pitch 66
    float* xa_T  = smem + 8576;      // 4 x [feat][node] pitch 66
    float* M_T   = smem + 25472;     // phase1: 4 x [in][out] pitch 66
    float* wbuf  = smem + 25472;     // phase2: 2 x 12288 (gate[p][128], cand @8192 [p][64])

    const int tid  = threadIdx.x;
    const int bt   = blockIdx.x;
    const int lane = tid & 31;
    const int g    = tid >> 5;           // warp 0..15

    const float* xsrc = (layer ? d_out0 : Xin) + (size_t)bt * 4096;

    for (int i = tid; i < 4096; i += 512) {
        int n = i >> 6, d = i & 63;
        float v = xsrc[i];
        x_row[n * 68 + d] = v;
        x_T[d * 66 + n]   = v;
    }
    for (int i = tid; i < 16384; i += 512) {
        int k = i >> 12, r = (i >> 6) & 63, c = i & 63;   // d_M[k][out=r][in=c]
        M_T[k * 4224 + c * 66 + r] = d_M[i];
    }
    __syncthreads();

    // ---------------- phase 1: xa_k = M_k @ x (stored transposed) ----------------
    // warp g: feature cols c4 = g*4; lane: out-rows {lane, lane+32}
    {
        const int c4 = g * 4;
        #pragma unroll
        for (int k = 0; k < 4; ++k) {
            const float* MT = M_T + k * 4224;
            u64t a00 = 0, a01 = 0, a10 = 0, a11 = 0;
            #pragma unroll 4
            for (int p = 0; p < 64; ++p) {
                u64t d0 = pack_dup(MT[p * 66 + lane]);
                u64t d1 = pack_dup(MT[p * 66 + lane + 32]);
                ulonglong2 xv = *(const ulonglong2*)(x_row + p * 68 + c4); // uniform
                fma2(a00, d0, xv.x); fma2(a01, d0, xv.y);
                fma2(a10, d1, xv.x); fma2(a11, d1, xv.y);
            }
            float* XT = xa_T + k * 4224;
            float2 v00 = unpack2(a00), v01 = unpack2(a01);
            float2 v10 = unpack2(a10), v11 = unpack2(a11);
            XT[(c4 + 0) * 66 + lane] = v00.x;
            XT[(c4 + 1) * 66 + lane] = v00.y;
            XT[(c4 + 2) * 66 + lane] = v01.x;
            XT[(c4 + 3) * 66 + lane] = v01.y;
            XT[(c4 + 0) * 66 + lane + 32] = v10.x;
            XT[(c4 + 1) * 66 + lane + 32] = v10.y;
            XT[(c4 + 2) * 66 + lane + 32] = v11.x;
            XT[(c4 + 3) * 66 + lane + 32] = v11.y;
        }
    }
    __syncthreads();   // M_T reads done -> wbuf may overwrite

    // ---------------- phase 2: Gx / Cx with cp.async'd W ----------------
    // warp g: gate cols [g*8, g*8+8), cand cols [g*4, g*4+4); rows lane & lane+32
    const int gb = g * 8;
    const int cb = g * 4;

    // prefetch k=0 W into buf 0
    {
        float* wb = wbuf;
        for (int i = tid; i < 2048; i += 512) cp16(wb + i * 4, Wg + i * 4);
        for (int i = tid; i < 1024; i += 512) cp16(wb + 8192 + i * 4, Wc + i * 4);
        CP_COMMIT();
    }

    u64t ag0[4], ag1[4], ac0[2], ac1[2];
    #pragma unroll
    for (int q = 0; q < 4; ++q) {
        u64t bb = pack2(bg[gb + 2 * q], bg[gb + 2 * q + 1]);
        ag0[q] = bb; ag1[q] = bb;
    }
    #pragma unroll
    for (int q = 0; q < 2; ++q) {
        u64t bb = pack2(bc[cb + 2 * q], bc[cb + 2 * q + 1]);
        ac0[q] = bb; ac1[q] = bb;
    }

    #pragma unroll
    for (int k = 0; k < 5; ++k) {
        if (k < 4) {
            float* wb = wbuf + ((k + 1) & 1) * 12288;
            const float* wgk = Wg + (size_t)((k + 1) * 128) * 128;
            const float* wck = Wc + (size_t)((k + 1) * 128) * 64;
            for (int i = tid; i < 2048; i += 512) cp16(wb + i * 4, wgk + i * 4);
            for (int i = tid; i < 1024; i += 512) cp16(wb + 8192 + i * 4, wck + i * 4);
        }
        CP_COMMIT();
        CP_WAIT1();        // buffer k ready (k+1 group may stay in flight)
        __syncthreads();

        const float* AT  = (k == 0) ? x_T : (xa_T + (k - 1) * 4224);
        const float* wgb = wbuf + (k & 1) * 12288 + gb;
        const float* wcb = wbuf + (k & 1) * 12288 + 8192 + cb;

        #pragma unroll 4
        for (int p = 0; p < 64; ++p) {
            u64t a0 = pack_dup(AT[p * 66 + lane]);        // conflict-free scalar
            u64t a1 = pack_dup(AT[p * 66 + lane + 32]);
            ulonglong2 w0 = *(const ulonglong2*)(wgb + p * 128);     // uniform
            ulonglong2 w1 = *(const ulonglong2*)(wgb + p * 128 + 4);
            ulonglong2 wc = *(const ulonglong2*)(wcb + p * 64);
            fma2(ag0[0], a0, w0.x); fma2(ag0[1], a0, w0.y);
            fma2(ag0[2], a0, w1.x); fma2(ag0[3], a0, w1.y);
            fma2(ag1[0], a1, w0.x); fma2(ag1[1], a1, w0.y);
            fma2(ag1[2], a1, w1.x); fma2(ag1[3], a1, w1.y);
            fma2(ac0[0], a0, wc.x); fma2(ac0[1], a0, wc.y);
            fma2(ac1[0], a1, wc.x); fma2(ac1[1], a1, wc.y);
        }
        __syncthreads();
    }

    float* gx = d_Gx + (size_t)bt * 8192;
    float* cx = d_Cx + (size_t)bt * 4096;
    ulonglong2 s;
    s.x = ag0[0]; s.y = ag0[1]; *(ulonglong2*)(gx + lane * 128 + gb)          = s;
    s.x = ag0[2]; s.y = ag0[3]; *(ulonglong2*)(gx + lane * 128 + gb + 4)      = s;
    s.x = ag1[0]; s.y = ag1[1]; *(ulonglong2*)(gx + (lane + 32) * 128 + gb)     = s;
    s.x = ag1[2]; s.y = ag1[3]; *(ulonglong2*)(gx + (lane + 32) * 128 + gb + 4) = s;
    s.x = ac0[0]; s.y = ac0[1]; *(ulonglong2*)(cx + lane * 64 + cb)           = s;
    s.x = ac1[0]; s.y = ac1[1]; *(ulonglong2*)(cx + (lane + 32) * 64 + cb)      = s;
}

// ---------------------------------------------------------------------------
// Persistent per-layer scan (h-half only). Grid 128 = 32 batches x cluster(4).
// v5: h/rh pitch 68 + float4 h loads in V-phases; split cluster barriers with
// rank-local exchange work overlapped between arrive and wait.
// smem (floats): wg_h 0(10240) wc_h 10240(5120) Ms 15360(17408)
//   h_s 32768(4352,p68) rh_s 37120(4352,p68) V_s 41472(11520)
//   rst 52992(1088) ugs 54080(1088) hst 55168(1088)  total 56256
// ---------------------------------------------------------------------------
#define SCAN_SMEM_BYTES (56256 * 4)

__global__ void __launch_bounds__(256, 1) __cluster_dims__(4, 1, 1)
scan_kernel(const float* __restrict__ Wg, const float* __restrict__ Wc,
            const int* __restrict__ lens, int layer)
{
    float* wg_h = smem;
    float* wc_h = smem + 10240;
    float* Ms   = smem + 15360;
    float* h_s  = smem + 32768;
    float* rh_s = smem + 37120;
    float* V_s  = smem + 41472;
    float* rst  = smem + 52992;
    float* ugs  = smem + 54080;
    float* hst  = smem + 55168;

    const int tid = threadIdx.x;
    const int b = blockIdx.x >> 2;
    const int j = blockIdx.x & 3;

    // one-time loads
    for (int i = tid; i < 10240; i += 256) {           // wg_h[k][d][c] = Wg[k*128+64+d][gmap]
        int k = i >> 11, d = (i >> 5) & 63, c = i & 31;
        int g = (c < 16) ? (j * 16 + c) : (64 + j * 16 + (c - 16));
        wg_h[i] = Wg[(size_t)(k * 128 + 64 + d) * 128 + g];
    }
    for (int i = tid; i < 5120; i += 256) {            // wc_h[k][d][c]
        int k = i >> 10, d = (i >> 4) & 63, c = i & 15;
        wc_h[i] = Wc[(size_t)(k * 128 + 64 + d) * 64 + j * 16 + c];
    }
    for (int i = tid; i < 16384; i += 256) {
        int k = i >> 12, r = (i >> 6) & 63, p = i & 63;
        Ms[k * 4352 + r * 68 + p] = d_M[i];
    }
    for (int i = tid; i < 4096; i += 256)
        h_s[(i >> 6) * 68 + (i & 63)] = 0.f;

    int idx_t = lens[b] - 1;
    idx_t = idx_t < 0 ? 0 : (idx_t > T_ - 1 ? T_ - 1 : idx_t);

    uint32_t rbase[4], hbase[4];
    #pragma unroll
    for (int r = 0; r < 4; ++r) {
        rbase[r] = mapa_rank(s_u32(rst), (uint32_t)r);
        hbase[r] = mapa_rank(s_u32(hst), (uint32_t)r);
    }

    const int rg  = tid & 31;
    const int jg  = tid >> 5;
    const int mg  = tid >> 3;
    const int ja4 = (tid & 7) * 4;
    const int ja2 = (tid & 7) * 2;
    const int g0  = (ja4 < 16) ? (j * 16 + ja4) : (64 + j * 16 + (ja4 - 16));
    const int c0  = j * 16 + ja2;

    const float* gxb = d_Gx + (size_t)b * T_ * 8192;
    const float* cxb = d_Cx + (size_t)b * T_ * 4096;

    for (int t = 0; t < T_; ++t) {
        __syncthreads();

        const float* gx = gxb + (size_t)t * 8192;
        const float* cx = cxb + (size_t)t * 4096;
        float4 gA = __ldg((const float4*)(gx + mg * 128 + g0));
        float4 gB = __ldg((const float4*)(gx + (mg + 32) * 128 + g0));
        float2 cA = __ldg((const float2*)(cx + mg * 64 + c0));
        float2 cB = __ldg((const float2*)(cx + (mg + 32) * 64 + c0));

        // ---------- gate V-phase: V_k = h @ wg_h[k], all 5 k ----------
        {
            u64t acc[5][4];
            #pragma unroll
            for (int k = 0; k < 5; ++k) { acc[k][0] = acc[k][1] = acc[k][2] = acc[k][3] = 0; }
            const float* h0p = h_s + rg * 68;
            const float* h1p = h_s + (rg + 32) * 68;
            const float* wbase = wg_h + jg * 4;
            #pragma unroll 2
            for (int d4 = 0; d4 < 64; d4 += 4) {
                float4 hv0 = *(const float4*)(h0p + d4);
                float4 hv1 = *(const float4*)(h1p + d4);
                float h0a[4] = {hv0.x, hv0.y, hv0.z, hv0.w};
                float h1a[4] = {hv1.x, hv1.y, hv1.z, hv1.w};
                #pragma unroll
                for (int q = 0; q < 4; ++q) {
                    u64t a0 = pack_dup(h0a[q]);
                    u64t a1 = pack_dup(h1a[q]);
                    #pragma unroll
                    for (int k = 0; k < 5; ++k) {
                        ulonglong2 w = *(const ulonglong2*)(wbase + k * 2048 + (d4 + q) * 32);
                        fma2(acc[k][0], a0, w.x); fma2(acc[k][1], a0, w.y);
                        fma2(acc[k][2], a1, w.x); fma2(acc[k][3], a1, w.y);
                    }
                }
            }
            #pragma unroll
            for (int k = 0; k < 5; ++k) {
                ulonglong2 s;
                s.x = acc[k][0]; s.y = acc[k][1];
                *(ulonglong2*)(V_s + k * 2304 + rg * 36 + jg * 4) = s;
                s.x = acc[k][2]; s.y = acc[k][3];
                *(ulonglong2*)(V_s + k * 2304 + (rg + 32) * 36 + jg * 4) = s;
            }
        }
        __syncthreads();

        // ---------- gate M-apply + sigmoid + stage ----------
        {
            float4 vA = *(const float4*)(V_s + mg * 36 + ja4);
            float4 vB = *(const float4*)(V_s + (mg + 32) * 36 + ja4);
            u64t y00 = pack2(gA.x + vA.x, gA.y + vA.y);
            u64t y01 = pack2(gA.z + vA.z, gA.w + vA.w);
            u64t y10 = pack2(gB.x + vB.x, gB.y + vB.y);
            u64t y11 = pack2(gB.z + vB.z, gB.w + vB.w);
            for (int k = 1; k < 5; ++k) {
                const float* Mk = Ms + (k - 1) * 4352;
                const float* Vk = V_s + k * 2304;
                #pragma unroll 4
                for (int m = 0; m < 64; m += 4) {
                    float4 mA = *(const float4*)(Mk + mg * 68 + m);
                    float4 mB = *(const float4*)(Mk + (mg + 32) * 68 + m);
                    float mAa[4] = {mA.x, mA.y, mA.z, mA.w};
                    float mBa[4] = {mB.x, mB.y, mB.z, mB.w};
                    #pragma unroll
                    for (int q = 0; q < 4; ++q) {
                        ulonglong2 v = *(const ulonglong2*)(Vk + (m + q) * 36 + ja4);
                        u64t da = pack_dup(mAa[q]);
                        u64t db = pack_dup(mBa[q]);
                        fma2(y00, da, v.x); fma2(y01, da, v.y);
                        fma2(y10, db, v.x); fma2(y11, db, v.y);
                    }
                }
            }
            float2 p00 = unpack2(y00), p01 = unpack2(y01);
            float2 p10 = unpack2(y10), p11 = unpack2(y11);
            float v0a[4] = {p00.x, p00.y, p01.x, p01.y};
            float v1a[4] = {p10.x, p10.y, p11.x, p11.y};
            #pragma unroll
            for (int q = 0; q < 4; ++q) {
                int c = ja4 + q;
                float s0 = sigmoid_f(v0a[q]);
                float s1 = sigmoid_f(v1a[q]);
                if (c < 16) { rst[mg * 17 + c] = s0;        rst[(mg + 32) * 17 + c] = s1; }
                else        { ugs[mg * 17 + c - 16] = s0;   ugs[(mg + 32) * 17 + c - 16] = s1; }
            }
        }

        // r exchange: arrive, do local quarter, wait, gather remote
        CLUSTER_ARRIVE();
        __syncthreads();            // local rst visible CTA-wide
        for (int i = tid; i < 1024; i += 256) {
            int n = i >> 4, dl = i & 15, d = j * 16 + dl;
            rh_s[n * 68 + d] = rst[n * 17 + dl] * h_s[n * 68 + d];
        }
        CLUSTER_WAIT();
        #pragma unroll
        for (int rr = 1; rr < 4; ++rr) {
            int rank = (j + rr) & 3;
            uint32_t rb = rbase[rank];
            for (int i = tid; i < 1024; i += 256) {
                int n = i >> 4, dl = i & 15, d = rank * 16 + dl;
                float r = ldc_f32(rb + (uint32_t)(n * 17 + dl) * 4);
                rh_s[n * 68 + d] = r * h_s[n * 68 + d];
            }
        }
        __syncthreads();

        // ---------- cand V-phase ----------
        {
            u64t acc[5][2];
            #pragma unroll
            for (int k = 0; k < 5; ++k) { acc[k][0] = acc[k][1] = 0; }
            const float* h0p = rh_s + rg * 68;
            const float* h1p = rh_s + (rg + 32) * 68;
            const float* wbase = wc_h + jg * 2;
            #pragma unroll 2
            for (int d4 = 0; d4 < 64; d4 += 4) {
                float4 hv0 = *(const float4*)(h0p + d4);
                float4 hv1 = *(const float4*)(h1p + d4);
                float h0a[4] = {hv0.x, hv0.y, hv0.z, hv0.w};
                float h1a[4] = {hv1.x, hv1.y, hv1.z, hv1.w};
                #pragma unroll
                for (int q = 0; q < 4; ++q) {
                    u64t a0 = pack_dup(h0a[q]);
                    u64t a1 = pack_dup(h1a[q]);
                    #pragma unroll
                    for (int k = 0; k < 5; ++k) {
                        u64t w = *(const u64t*)(wbase + k * 1024 + (d4 + q) * 16);
                        fma2(acc[k][0], a0, w);
                        fma2(acc[k][1], a1, w);
                    }
                }
            }
            #pragma unroll
            for (int k = 0; k < 5; ++k) {
                *(u64t*)(V_s + k * 2304 + rg * 36 + jg * 2)        = acc[k][0];
                *(u64t*)(V_s + k * 2304 + (rg + 32) * 36 + jg * 2) = acc[k][1];
            }
        }
        __syncthreads();

        // ---------- cand M-apply + GRU update ----------
        {
            float2 v0 = *(const float2*)(V_s + mg * 36 + ja2);
            float2 v1 = *(const float2*)(V_s + (mg + 32) * 36 + ja2);
            u64t y0 = pack2(cA.x + v0.x, cA.y + v0.y);
            u64t y1 = pack2(cB.x + v1.x, cB.y + v1.y);
            for (int k = 1; k < 5; ++k) {
                const float* Mk = Ms + (k - 1) * 4352;
                const float* Vk = V_s + k * 2304;
                #pragma unroll 4
                for (int m = 0; m < 64; m += 4) {
                    float4 mA = *(const float4*)(Mk + mg * 68 + m);
                    float4 mB = *(const float4*)(Mk + (mg + 32) * 68 + m);
                    float mAa[4] = {mA.x, mA.y, mA.z, mA.w};
                    float mBa[4] = {mB.x, mB.y, mB.z, mB.w};
                    #pragma unroll
                    for (int q = 0; q < 4; ++q) {
                        u64t v = *(const u64t*)(Vk + (m + q) * 36 + ja2);
                        fma2(y0, pack_dup(mAa[q]), v);
                        fma2(y1, pack_dup(mBa[q]), v);
                    }
                }
            }
            float* hout0 = d_out0 + ((size_t)(b * T_ + t)) * 4096;
            float2 cc0 = unpack2(y0), cc1 = unpack2(y1);
            float cand0[2] = {cc0.x, cc0.y};
            float cand1[2] = {cc1.x, cc1.y};
            #pragma unroll
            for (int q = 0; q < 2; ++q) {
                int cl = ja2 + q;
                int col = j * 16 + cl;
                float cv0 = tanh_f(cand0[q]);
                float ug0 = ugs[mg * 17 + cl];
                float hn0 = ug0 * h_s[mg * 68 + col] + (1.f - ug0) * cv0;
                hst[mg * 17 + cl] = hn0;
                float cv1 = tanh_f(cand1[q]);
                float ug1 = ugs[(mg + 32) * 17 + cl];
                float hn1 = ug1 * h_s[(mg + 32) * 68 + col] + (1.f - ug1) * cv1;
                hst[(mg + 32) * 17 + cl] = hn1;
                if (layer == 0) {
                    hout0[mg * 64 + col]        = hn0;
                    hout0[(mg + 32) * 64 + col] = hn1;
                } else if (t == idx_t) {
                    d_last[(size_t)b * 4096 + mg * 64 + col]        = hn0;
                    d_last[(size_t)b * 4096 + (mg + 32) * 64 + col] = hn1;
                }
            }
        }

        // h exchange: arrive, local quarter, wait, gather remote
        CLUSTER_ARRIVE();
        __syncthreads();
        for (int i = tid; i < 1024; i += 256) {
            int n = i >> 4, dl = i & 15;
            h_s[n * 68 + j * 16 + dl] = hst[n * 17 + dl];
        }
        CLUSTER_WAIT();
        #pragma unroll
        for (int rr = 1; rr < 4; ++rr) {
            int rank = (j + rr) & 3;
            uint32_t hb = hbase[rank];
            for (int i = tid; i < 1024; i += 256) {
                int n = i >> 4, dl = i & 15;
                h_s[n * 68 + rank * 16 + dl] = ldc_f32(hb + (uint32_t)(n * 17 + dl) * 4);
            }
        }
    }
    CLUSTER_SYNC();   // no CTA exits while peers may still read its DSMEM
}

// ---------------------------------------------------------------------------
// Final projection + node max-pool
// ---------------------------------------------------------------------------
__global__ void final_kernel(const float* __restrict__ Wp, const float* __restrict__ bp,
                             float* __restrict__ out)
{
    __shared__ float red[64 * 4];
    const int b = blockIdx.x, n = threadIdx.x;
    const float* h = d_last + (size_t)b * 4096 + n * 64;
    float l0 = bp[0], l1 = bp[1], l2 = bp[2], l3 = bp[3];
    #pragma unroll 8
    for (int d = 0; d < 64; ++d) {
        float v = fmaxf(h[d], 0.f);
        l0 += v * Wp[d * 4 + 0];
        l1 += v * Wp[d * 4 + 1];
        l2 += v * Wp[d * 4 + 2];
        l3 += v * Wp[d * 4 + 3];
    }
    red[n * 4 + 0] = l0; red[n * 4 + 1] = l1; red[n * 4 + 2] = l2; red[n * 4 + 3] = l3;
    __syncthreads();
    for (int s = 32; s > 0; s >>= 1) {
        if (n < s) {
            #pragma unroll
            for (int c = 0; c < 4; ++c)
                red[n * 4 + c] = fmaxf(red[n * 4 + c], red[(n + s) * 4 + c]);
        }
        __syncthreads();
    }
    if (n < 4) out[b * 4 + n] = red[n];
}

// ---------------------------------------------------------------------------
extern "C" void kernel_launch(void* const* d_in, const int* in_sizes, int n_in,
                              void* d_out, int out_size)
{
    (void)in_sizes; (void)n_in; (void)out_size;
    const float* X   = (const float*)d_in[0];
    const int*   len = (const int*)  d_in[1];
    const float* S0  = (const float*)d_in[2];
    const float* S1  = (const float*)d_in[3];
    const float* Wg0 = (const float*)d_in[4];
    const float* bg0 = (const float*)d_in[5];
    const float* Wc0 = (const float*)d_in[6];
    const float* bc0 = (const float*)d_in[7];
    const float* Wg1 = (const float*)d_in[8];
    const float* bg1 = (const float*)d_in[9];
    const float* Wc1 = (const float*)d_in[10];
    const float* bc1 = (const float*)d_in[11];
    const float* Wp  = (const float*)d_in[12];
    const float* bp  = (const float*)d_in[13];
    float* out = (float*)d_out;

    cudaFuncSetAttribute(pre_kernel,  cudaFuncAttributeMaxDynamicSharedMemorySize, PRE_SMEM_BYTES);
    cudaFuncSetAttribute(scan_kernel, cudaFuncAttributeMaxDynamicSharedMemorySize, SCAN_SMEM_BYTES);

    prep_kernel<<<2, 256>>>(S0, S1);
    pre_kernel<<<B_ * T_, 512, PRE_SMEM_BYTES>>>(X, Wg0, bg0, Wc0, bc0, 0);
    scan_kernel<<<128, 256, SCAN_SMEM_BYTES>>>(Wg0, Wc0, len, 0);
    pre_kernel<<<B_ * T_, 512, PRE_SMEM_BYTES>>>(X, Wg1, bg1, Wc1, bc1, 1);
    scan_kernel<<<128, 256, SCAN_SMEM_BYTES>>>(Wg1, Wc1, len, 1);
    final_kernel<<<B_, 64>>>(Wp, bp, out);
}

// round 9
// speedup vs baseline: 1.3137x; 1.0131x over previous
#include <cuda_runtime.h>
#include <math.h>
#include <stdint.h>

#define B_ 32
#define T_ 128

typedef unsigned long long u64t;

// Scratch (device globals: allocation-free)
__device__ float d_M[4 * 4096];                 // S0, 2S0^2-I, S1, 2S1^2-I
__device__ float d_out0[B_ * T_ * 4096];        // layer-0 h states
__device__ float d_last[B_ * 4096];             // layer-1 h at last relevant t
__device__ float d_Gx[(size_t)B_ * T_ * 64 * 128]; // gate x-part preactivations (+bias)
__device__ float d_Cx[(size_t)B_ * T_ * 64 * 64];  // cand x-part preactivations (+bias)

// ---------------- f32x2 helpers ----------------
__device__ __forceinline__ u64t pack_dup(float x) {
    u64t r; asm("mov.b64 %0, {%1,%1};" : "=l"(r) : "f"(x)); return r;
}
__device__ __forceinline__ u64t pack2(float lo, float hi) {
    u64t r; asm("mov.b64 %0, {%1,%2};" : "=l"(r) : "f"(lo), "f"(hi)); return r;
}
__device__ __forceinline__ float2 unpack2(u64t v) {
    float2 f; asm("mov.b64 {%0,%1}, %2;" : "=f"(f.x), "=f"(f.y) : "l"(v)); return f;
}
__device__ __forceinline__ void fma2(u64t& d, u64t a, u64t b) {
    asm("fma.rn.f32x2 %0, %1, %2, %0;" : "+l"(d) : "l"(a), "l"(b));
}

__device__ __forceinline__ uint32_t s_u32(const void* p) {
    return (uint32_t)__cvta_generic_to_shared(p);
}
__device__ __forceinline__ uint32_t mapa_rank(uint32_t a, uint32_t r) {
    uint32_t o;
    asm("mapa.shared::cluster.u32 %0, %1, %2;" : "=r"(o) : "r"(a), "r"(r));
    return o;
}
__device__ __forceinline__ float ldc_f32(uint32_t a) {
    float v;
    asm volatile("ld.shared::cluster.f32 %0, [%1];" : "=f"(v) : "r"(a));
    return v;
}
__device__ __forceinline__ void cp16(float* dst, const float* src) {
    asm volatile("cp.async.cg.shared.global [%0], [%1], 16;"
                 :: "r"(s_u32(dst)), "l"(src));
}
#define CP_COMMIT() asm volatile("cp.async.commit_group;")
#define CP_WAIT1()  asm volatile("cp.async.wait_group 1;")
#define CLUSTER_ARRIVE() asm volatile("barrier.cluster.arrive.aligned;" ::: "memory")
#define CLUSTER_WAIT()   asm volatile("barrier.cluster.wait.aligned;"   ::: "memory")
#define CLUSTER_SYNC() do { CLUSTER_ARRIVE(); CLUSTER_WAIT(); } while (0)

// fast activations (bounded preactivations; __expf/__fdividef err ~1e-6 rel)
__device__ __forceinline__ float sigmoid_f(float v) {
    return __fdividef(1.f, 1.f + __expf(-v));
}
__device__ __forceinline__ float tanh_f(float v) {
    return 1.f - __fdividef(2.f, __expf(2.f * v) + 1.f);
}

extern __shared__ float smem[];

// ---------------------------------------------------------------------------
// Precompute diffusion operators.
// ---------------------------------------------------------------------------
__global__ void prep_kernel(const float* __restrict__ S0, const float* __restrict__ S1)
{
    __shared__ float Ss[64 * 64];
    const int s = blockIdx.x;
    const float* S = s ? S1 : S0;
    for (int i = threadIdx.x; i < 4096; i += blockDim.x) Ss[i] = S[i];
    __syncthreads();
    for (int i = threadIdx.x; i < 4096; i += blockDim.x) {
        int m = i >> 6, n = i & 63;
        float acc = 0.f;
        #pragma unroll 8
        for (int p = 0; p < 64; ++p) acc += Ss[m * 64 + p] * Ss[p * 64 + n];
        d_M[(2 * s) * 4096 + i]     = Ss[i];
        d_M[(2 * s + 1) * 4096 + i] = 2.f * acc - (m == n ? 1.f : 0.f);
    }
}

// ---------------------------------------------------------------------------
// Precompute x-contributions for every (b,t). (R8 version, unchanged)
// ---------------------------------------------------------------------------
#define PRE_SMEM_FLOATS 50048
#define PRE_SMEM_BYTES (PRE_SMEM_FLOATS * 4)

__global__ void __launch_bounds__(512, 1)
pre_kernel(const float* __restrict__ Xin,
           const float* __restrict__ Wg, const float* __restrict__ bg,
           const float* __restrict__ Wc, const float* __restrict__ bc,
           int layer)
{
    float* x_row = smem;             // [node][feat] pitch 68 (uniform vec reads)
    float* x_T   = smem + 4352;      // [feat][node] pitch 66
    float* xa_T  = smem + 8576;      // 4 x [feat][node] pitch 66
    float* M_T   = smem + 25472;     // phase1: 4 x [in][out] pitch 66
    float* wbuf  = smem + 25472;     // phase2: 2 x 12288 (gate[p][128], cand @8192 [p][64])

    const int tid  = threadIdx.x;
    const int bt   = blockIdx.x;
    const int lane = tid & 31;
    const int g    = tid >> 5;           // warp 0..15

    const float* xsrc = (layer ? d_out0 : Xin) + (size_t)bt * 4096;

    for (int i = tid; i < 4096; i += 512) {
        int n = i >> 6, d = i & 63;
        float v = xsrc[i];
        x_row[n * 68 + d] = v;
        x_T[d * 66 + n]   = v;
    }
    for (int i = tid; i < 16384; i += 512) {
        int k = i >> 12, r = (i >> 6) & 63, c = i & 63;   // d_M[k][out=r][in=c]
        M_T[k * 4224 + c * 66 + r] = d_M[i];
    }
    __syncthreads();

    // ---------------- phase 1: xa_k = M_k @ x (stored transposed) ----------------
    {
        const int c4 = g * 4;
        #pragma unroll
        for (int k = 0; k < 4; ++k) {
            const float* MT = M_T + k * 4224;
            u64t a00 = 0, a01 = 0, a10 = 0, a11 = 0;
            #pragma unroll 4
            for (int p = 0; p < 64; ++p) {
                u64t d0 = pack_dup(MT[p * 66 + lane]);
                u64t d1 = pack_dup(MT[p * 66 + lane + 32]);
                ulonglong2 xv = *(const ulonglong2*)(x_row + p * 68 + c4); // uniform
                fma2(a00, d0, xv.x); fma2(a01, d0, xv.y);
                fma2(a10, d1, xv.x); fma2(a11, d1, xv.y);
            }
            float* XT = xa_T + k * 4224;
            float2 v00 = unpack2(a00), v01 = unpack2(a01);
            float2 v10 = unpack2(a10), v11 = unpack2(a11);
            XT[(c4 + 0) * 66 + lane] = v00.x;
            XT[(c4 + 1) * 66 + lane] = v00.y;
            XT[(c4 + 2) * 66 + lane] = v01.x;
            XT[(c4 + 3) * 66 + lane] = v01.y;
            XT[(c4 + 0) * 66 + lane + 32] = v10.x;
            XT[(c4 + 1) * 66 + lane + 32] = v10.y;
            XT[(c4 + 2) * 66 + lane + 32] = v11.x;
            XT[(c4 + 3) * 66 + lane + 32] = v11.y;
        }
    }
    __syncthreads();   // M_T reads done -> wbuf may overwrite

    // ---------------- phase 2: Gx / Cx with cp.async'd W ----------------
    const int gb = g * 8;
    const int cb = g * 4;

    {
        float* wb = wbuf;
        for (int i = tid; i < 2048; i += 512) cp16(wb + i * 4, Wg + i * 4);
        for (int i = tid; i < 1024; i += 512) cp16(wb + 8192 + i * 4, Wc + i * 4);
        CP_COMMIT();
    }

    u64t ag0[4], ag1[4], ac0[2], ac1[2];
    #pragma unroll
    for (int q = 0; q < 4; ++q) {
        u64t bb = pack2(bg[gb + 2 * q], bg[gb + 2 * q + 1]);
        ag0[q] = bb; ag1[q] = bb;
    }
    #pragma unroll
    for (int q = 0; q < 2; ++q) {
        u64t bb = pack2(bc[cb + 2 * q], bc[cb + 2 * q + 1]);
        ac0[q] = bb; ac1[q] = bb;
    }

    #pragma unroll
    for (int k = 0; k < 5; ++k) {
        if (k < 4) {
            float* wb = wbuf + ((k + 1) & 1) * 12288;
            const float* wgk = Wg + (size_t)((k + 1) * 128) * 128;
            const float* wck = Wc + (size_t)((k + 1) * 128) * 64;
            for (int i = tid; i < 2048; i += 512) cp16(wb + i * 4, wgk + i * 4);
            for (int i = tid; i < 1024; i += 512) cp16(wb + 8192 + i * 4, wck + i * 4);
        }
        CP_COMMIT();
        CP_WAIT1();
        __syncthreads();

        const float* AT  = (k == 0) ? x_T : (xa_T + (k - 1) * 4224);
        const float* wgb = wbuf + (k & 1) * 12288 + gb;
        const float* wcb = wbuf + (k & 1) * 12288 + 8192 + cb;

        #pragma unroll 4
        for (int p = 0; p < 64; ++p) {
            u64t a0 = pack_dup(AT[p * 66 + lane]);
            u64t a1 = pack_dup(AT[p * 66 + lane + 32]);
            ulonglong2 w0 = *(const ulonglong2*)(wgb + p * 128);
            ulonglong2 w1 = *(const ulonglong2*)(wgb + p * 128 + 4);
            ulonglong2 wc = *(const ulonglong2*)(wcb + p * 64);
            fma2(ag0[0], a0, w0.x); fma2(ag0[1], a0, w0.y);
            fma2(ag0[2], a0, w1.x); fma2(ag0[3], a0, w1.y);
            fma2(ag1[0], a1, w0.x); fma2(ag1[1], a1, w0.y);
            fma2(ag1[2], a1, w1.x); fma2(ag1[3], a1, w1.y);
            fma2(ac0[0], a0, wc.x); fma2(ac0[1], a0, wc.y);
            fma2(ac1[0], a1, wc.x); fma2(ac1[1], a1, wc.y);
        }
        __syncthreads();
    }

    float* gx = d_Gx + (size_t)bt * 8192;
    float* cx = d_Cx + (size_t)bt * 4096;
    ulonglong2 s;
    s.x = ag0[0]; s.y = ag0[1]; *(ulonglong2*)(gx + lane * 128 + gb)          = s;
    s.x = ag0[2]; s.y = ag0[3]; *(ulonglong2*)(gx + lane * 128 + gb + 4)      = s;
    s.x = ag1[0]; s.y = ag1[1]; *(ulonglong2*)(gx + (lane + 32) * 128 + gb)     = s;
    s.x = ag1[2]; s.y = ag1[3]; *(ulonglong2*)(gx + (lane + 32) * 128 + gb + 4) = s;
    s.x = ac0[0]; s.y = ac0[1]; *(ulonglong2*)(cx + lane * 64 + cb)           = s;
    s.x = ac1[0]; s.y = ac1[1]; *(ulonglong2*)(cx + (lane + 32) * 64 + cb)      = s;
}

// ---------------------------------------------------------------------------
// Persistent per-layer scan. Grid 128 = 32 batches x cluster(4).
// v6: 512 threads. V-phases split by INNER dim d (each half 32 d's) -> per-SMSP
// LDS and fma2 totals identical to the 256-thread version, warps doubled.
// Half-0 stores V, half-1 RMW-adds its partial. M-apply split by k
// (half0: base+k1,k2; half1: k3,k4) with 8-float partial exchange through the
// dead rh_s window. Smem layout identical to R8.
// ---------------------------------------------------------------------------
#define SCAN_SMEM_BYTES (56256 * 4)

__global__ void __launch_bounds__(512, 1) __cluster_dims__(4, 1, 1)
scan_kernel(const float* __restrict__ Wg, const float* __restrict__ Wc,
            const int* __restrict__ lens, int layer)
{
    float* wg_h = smem;
    float* wc_h = smem + 10240;
    float* Ms   = smem + 15360;
    float* h_s  = smem + 32768;   // pitch 68
    float* rh_s = smem + 37120;   // pitch 68; also yP partial overlay
    float* V_s  = smem + 41472;   // 5 x 64 x 36
    float* rst  = smem + 52992;
    float* ugs  = smem + 54080;
    float* hst  = smem + 55168;
    float* yP   = rh_s;           // partial-y overlay (rh dead in those windows)

    const int tid = threadIdx.x;
    const int b = blockIdx.x >> 2;
    const int j = blockIdx.x & 3;

    // one-time loads
    for (int i = tid; i < 10240; i += 512) {
        int k = i >> 11, d = (i >> 5) & 63, c = i & 31;
        int g = (c < 16) ? (j * 16 + c) : (64 + j * 16 + (c - 16));
        wg_h[i] = Wg[(size_t)(k * 128 + 64 + d) * 128 + g];
    }
    for (int i = tid; i < 5120; i += 512) {
        int k = i >> 10, d = (i >> 4) & 63, c = i & 15;
        wc_h[i] = Wc[(size_t)(k * 128 + 64 + d) * 64 + j * 16 + c];
    }
    for (int i = tid; i < 16384; i += 512) {
        int k = i >> 12, r = (i >> 6) & 63, p = i & 63;
        Ms[k * 4352 + r * 68 + p] = d_M[i];
    }
    for (int i = tid; i < 4096; i += 512)
        h_s[(i >> 6) * 68 + (i & 63)] = 0.f;

    int idx_t = lens[b] - 1;
    idx_t = idx_t < 0 ? 0 : (idx_t > T_ - 1 ? T_ - 1 : idx_t);

    uint32_t rbase[4], hbase[4];
    #pragma unroll
    for (int r = 0; r < 4; ++r) {
        rbase[r] = mapa_rank(s_u32(rst), (uint32_t)r);
        hbase[r] = mapa_rank(s_u32(hst), (uint32_t)r);
    }

    const int rg  = tid & 31;            // V-phase row
    const int jg  = (tid >> 5) & 7;      // V-phase col group
    const int dh  = tid >> 8;            // inner-dim half / k-half
    const int s5  = tid & 255;           // M-apply sub-id
    const int mg  = s5 >> 3;             // M-apply row (0..31), rows {mg, mg+32}
    const int ja4 = (s5 & 7) * 4;
    const int ja2 = (s5 & 7) * 2;
    const int g0  = (ja4 < 16) ? (j * 16 + ja4) : (64 + j * 16 + (ja4 - 16));
    const int c0  = j * 16 + ja2;
    const u64t ONE = pack_dup(1.f);

    const float* gxb = d_Gx + (size_t)b * T_ * 8192;
    const float* cxb = d_Cx + (size_t)b * T_ * 4096;

    for (int t = 0; t < T_; ++t) {
        __syncthreads();

        float4 gA = make_float4(0.f, 0.f, 0.f, 0.f);
        float4 gB = gA;
        float2 cA = make_float2(0.f, 0.f);
        float2 cB = cA;
        if (dh == 0) {
            const float* gx = gxb + (size_t)t * 8192;
            const float* cx = cxb + (size_t)t * 4096;
            gA = __ldg((const float4*)(gx + mg * 128 + g0));
            gB = __ldg((const float4*)(gx + (mg + 32) * 128 + g0));
            cA = __ldg((const float2*)(cx + mg * 64 + c0));
            cB = __ldg((const float2*)(cx + (mg + 32) * 64 + c0));
        }

        // ---------- gate V-phase (d-split) ----------
        {
            u64t acc[5][4];
            #pragma unroll
            for (int k = 0; k < 5; ++k) { acc[k][0] = acc[k][1] = acc[k][2] = acc[k][3] = 0; }
            const float* h0p = h_s + rg * 68 + dh * 32;
            const float* h1p = h_s + (rg + 32) * 68 + dh * 32;
            const float* wbase = wg_h + jg * 4 + dh * 1024;   // (dh*32 + d) * 32
            #pragma unroll 2
            for (int d4 = 0; d4 < 32; d4 += 4) {
                float4 hv0 = *(const float4*)(h0p + d4);
                float4 hv1 = *(const float4*)(h1p + d4);
                float h0a[4] = {hv0.x, hv0.y, hv0.z, hv0.w};
                float h1a[4] = {hv1.x, hv1.y, hv1.z, hv1.w};
                #pragma unroll
                for (int q = 0; q < 4; ++q) {
                    u64t a0 = pack_dup(h0a[q]);
                    u64t a1 = pack_dup(h1a[q]);
                    #pragma unroll
                    for (int k = 0; k < 5; ++k) {
                        ulonglong2 w = *(const ulonglong2*)(wbase + k * 2048 + (d4 + q) * 32);
                        fma2(acc[k][0], a0, w.x); fma2(acc[k][1], a0, w.y);
                        fma2(acc[k][2], a1, w.x); fma2(acc[k][3], a1, w.y);
                    }
                }
            }
            if (dh == 0) {
                #pragma unroll
                for (int k = 0; k < 5; ++k) {
                    ulonglong2 sv;
                    sv.x = acc[k][0]; sv.y = acc[k][1];
                    *(ulonglong2*)(V_s + k * 2304 + rg * 36 + jg * 4) = sv;
                    sv.x = acc[k][2]; sv.y = acc[k][3];
                    *(ulonglong2*)(V_s + k * 2304 + (rg + 32) * 36 + jg * 4) = sv;
                }
            }
            __syncthreads();
            if (dh == 1) {
                #pragma unroll
                for (int k = 0; k < 5; ++k) {
                    float* p0 = V_s + k * 2304 + rg * 36 + jg * 4;
                    float* p1 = V_s + k * 2304 + (rg + 32) * 36 + jg * 4;
                    ulonglong2 c0v = *(ulonglong2*)p0;
                    ulonglong2 c1v = *(ulonglong2*)p1;
                    fma2(c0v.x, ONE, acc[k][0]); fma2(c0v.y, ONE, acc[k][1]);
                    fma2(c1v.x, ONE, acc[k][2]); fma2(c1v.y, ONE, acc[k][3]);
                    *(ulonglong2*)p0 = c0v;
                    *(ulonglong2*)p1 = c1v;
                }
            }
            __syncthreads();
        }

        // ---------- gate M-apply (k-split) + sigmoid + stage ----------
        {
            u64t y00, y01, y10, y11;
            if (dh == 0) {
                float4 vA = *(const float4*)(V_s + mg * 36 + ja4);
                float4 vB = *(const float4*)(V_s + (mg + 32) * 36 + ja4);
                y00 = pack2(gA.x + vA.x, gA.y + vA.y);
                y01 = pack2(gA.z + vA.z, gA.w + vA.w);
                y10 = pack2(gB.x + vB.x, gB.y + vB.y);
                y11 = pack2(gB.z + vB.z, gB.w + vB.w);
            } else {
                y00 = y01 = y10 = y11 = pack_dup(0.f);
            }
            const int kb = 1 + dh * 2;     // 1 or 3
            #pragma unroll
            for (int kk = 0; kk < 2; ++kk) {
                const float* Mk = Ms + (kb - 1 + kk) * 4352;
                const float* Vk = V_s + (kb + kk) * 2304;
                #pragma unroll 4
                for (int m = 0; m < 64; m += 4) {
                    float4 mA = *(const float4*)(Mk + mg * 68 + m);
                    float4 mB = *(const float4*)(Mk + (mg + 32) * 68 + m);
                    float mAa[4] = {mA.x, mA.y, mA.z, mA.w};
                    float mBa[4] = {mB.x, mB.y, mB.z, mB.w};
                    #pragma unroll
                    for (int q = 0; q < 4; ++q) {
                        ulonglong2 v = *(const ulonglong2*)(Vk + (m + q) * 36 + ja4);
                        u64t da = pack_dup(mAa[q]);
                        u64t db = pack_dup(mBa[q]);
                        fma2(y00, da, v.x); fma2(y01, da, v.y);
                        fma2(y10, db, v.x); fma2(y11, db, v.y);
                    }
                }
            }
            if (dh == 1) {
                ulonglong2 sv;
                sv.x = y00; sv.y = y01; *(ulonglong2*)(yP + s5 * 8)     = sv;
                sv.x = y10; sv.y = y11; *(ulonglong2*)(yP + s5 * 8 + 4) = sv;
            }
            __syncthreads();
            if (dh == 0) {
                ulonglong2 pa = *(const ulonglong2*)(yP + s5 * 8);
                ulonglong2 pb = *(const ulonglong2*)(yP + s5 * 8 + 4);
                fma2(y00, ONE, pa.x); fma2(y01, ONE, pa.y);
                fma2(y10, ONE, pb.x); fma2(y11, ONE, pb.y);
                float2 p00 = unpack2(y00), p01 = unpack2(y01);
                float2 p10 = unpack2(y10), p11 = unpack2(y11);
                float v0a[4] = {p00.x, p00.y, p01.x, p01.y};
                float v1a[4] = {p10.x, p10.y, p11.x, p11.y};
                #pragma unroll
                for (int q = 0; q < 4; ++q) {
                    int c = ja4 + q;
                    float s0 = sigmoid_f(v0a[q]);
                    float s1 = sigmoid_f(v1a[q]);
                    if (c < 16) { rst[mg * 17 + c] = s0;        rst[(mg + 32) * 17 + c] = s1; }
                    else        { ugs[mg * 17 + c - 16] = s0;   ugs[(mg + 32) * 17 + c - 16] = s1; }
                }
            }
            __syncthreads();
        }

        // r exchange: arrive, local quarter, wait, gather remote
        CLUSTER_ARRIVE();
        for (int i = tid; i < 1024; i += 512) {
            int n = i >> 4, dl = i & 15, d = j * 16 + dl;
            rh_s[n * 68 + d] = rst[n * 17 + dl] * h_s[n * 68 + d];
        }
        CLUSTER_WAIT();
        #pragma unroll
        for (int rr = 1; rr < 4; ++rr) {
            int rank = (j + rr) & 3;
            uint32_t rb = rbase[rank];
            for (int i = tid; i < 1024; i += 512) {
                int n = i >> 4, dl = i & 15, d = rank * 16 + dl;
                float r = ldc_f32(rb + (uint32_t)(n * 17 + dl) * 4);
                rh_s[n * 68 + d] = r * h_s[n * 68 + d];
            }
        }
        __syncthreads();

        // ---------- cand V-phase (d-split) ----------
        {
            u64t acc[5][2];
            #pragma unroll
            for (int k = 0; k < 5; ++k) { acc[k][0] = acc[k][1] = 0; }
            const float* h0p = rh_s + rg * 68 + dh * 32;
            const float* h1p = rh_s + (rg + 32) * 68 + dh * 32;
            const float* wbase = wc_h + jg * 2 + dh * 512;    // (dh*32 + d) * 16
            #pragma unroll 2
            for (int d4 = 0; d4 < 32; d4 += 4) {
                float4 hv0 = *(const float4*)(h0p + d4);
                float4 hv1 = *(const float4*)(h1p + d4);
                float h0a[4] = {hv0.x, hv0.y, hv0.z, hv0.w};
                float h1a[4] = {hv1.x, hv1.y, hv1.z, hv1.w};
                #pragma unroll
                for (int q = 0; q < 4; ++q) {
                    u64t a0 = pack_dup(h0a[q]);
                    u64t a1 = pack_dup(h1a[q]);
                    #pragma unroll
                    for (int k = 0; k < 5; ++k) {
                        u64t w = *(const u64t*)(wbase + k * 1024 + (d4 + q) * 16);
                        fma2(acc[k][0], a0, w);
                        fma2(acc[k][1], a1, w);
                    }
                }
            }
            if (dh == 0) {
                #pragma unroll
                for (int k = 0; k < 5; ++k) {
                    *(u64t*)(V_s + k * 2304 + rg * 36 + jg * 2)        = acc[k][0];
                    *(u64t*)(V_s + k * 2304 + (rg + 32) * 36 + jg * 2) = acc[k][1];
                }
            }
            __syncthreads();
            if (dh == 1) {
                #pragma unroll
                for (int k = 0; k < 5; ++k) {
                    float* p0 = V_s + k * 2304 + rg * 36 + jg * 2;
                    float* p1 = V_s + k * 2304 + (rg + 32) * 36 + jg * 2;
                    u64t c0v = *(u64t*)p0;
                    u64t c1v = *(u64t*)p1;
                    fma2(c0v, ONE, acc[k][0]);
                    fma2(c1v, ONE, acc[k][1]);
                    *(u64t*)p0 = c0v;
                    *(u64t*)p1 = c1v;
                }
            }
            __syncthreads();
        }

        // ---------- cand M-apply (k-split) + GRU update ----------
        {
            u64t y0, y1;
            if (dh == 0) {
                float2 v0 = *(const float2*)(V_s + mg * 36 + ja2);
                float2 v1 = *(const float2*)(V_s + (mg + 32) * 36 + ja2);
                y0 = pack2(cA.x + v0.x, cA.y + v0.y);
                y1 = pack2(cB.x + v1.x, cB.y + v1.y);
            } else {
                y0 = y1 = pack_dup(0.f);
            }
            const int kb = 1 + dh * 2;
            #pragma unroll
            for (int kk = 0; kk < 2; ++kk) {
                const float* Mk = Ms + (kb - 1 + kk) * 4352;
                const float* Vk = V_s + (kb + kk) * 2304;
                #pragma unroll 4
                for (int m = 0; m < 64; m += 4) {
                    float4 mA = *(const float4*)(Mk + mg * 68 + m);
                    float4 mB = *(const float4*)(Mk + (mg + 32) * 68 + m);
                    float mAa[4] = {mA.x, mA.y, mA.z, mA.w};
                    float mBa[4] = {mB.x, mB.y, mB.z, mB.w};
                    #pragma unroll
                    for (int q = 0; q < 4; ++q) {
                        u64t v = *(const u64t*)(Vk + (m + q) * 36 + ja2);
                        fma2(y0, pack_dup(mAa[q]), v);
                        fma2(y1, pack_dup(mBa[q]), v);
                    }
                }
            }
            if (dh == 1) {
                *(u64t*)(yP + s5 * 4)     = y0;
                *(u64t*)(yP + s5 * 4 + 2) = y1;
            }
            __syncthreads();
            if (dh == 0) {
                u64t pa = *(const u64t*)(yP + s5 * 4);
                u64t pb = *(const u64t*)(yP + s5 * 4 + 2);
                fma2(y0, ONE, pa);
                fma2(y1, ONE, pb);
                float* hout0 = d_out0 + ((size_t)(b * T_ + t)) * 4096;
                float2 cc0 = unpack2(y0), cc1 = unpack2(y1);
                float cand0[2] = {cc0.x, cc0.y};
                float cand1[2] = {cc1.x, cc1.y};
                #pragma unroll
                for (int q = 0; q < 2; ++q) {
                    int cl = ja2 + q;
                    int col = j * 16 + cl;
                    float cv0 = tanh_f(cand0[q]);
                    float ug0 = ugs[mg * 17 + cl];
                    float hn0 = ug0 * h_s[mg * 68 + col] + (1.f - ug0) * cv0;
                    hst[mg * 17 + cl] = hn0;
                    float cv1 = tanh_f(cand1[q]);
                    float ug1 = ugs[(mg + 32) * 17 + cl];
                    float hn1 = ug1 * h_s[(mg + 32) * 68 + col] + (1.f - ug1) * cv1;
                    hst[(mg + 32) * 17 + cl] = hn1;
                    if (layer == 0) {
                        hout0[mg * 64 + col]        = hn0;
                        hout0[(mg + 32) * 64 + col] = hn1;
                    } else if (t == idx_t) {
                        d_last[(size_t)b * 4096 + mg * 64 + col]        = hn0;
                        d_last[(size_t)b * 4096 + (mg + 32) * 64 + col] = hn1;
                    }
                }
            }
            __syncthreads();
        }

        // h exchange: arrive, local quarter, wait, gather remote
        CLUSTER_ARRIVE();
        for (int i = tid; i < 1024; i += 512) {
            int n = i >> 4, dl = i & 15;
            h_s[n * 68 + j * 16 + dl] = hst[n * 17 + dl];
        }
        CLUSTER_WAIT();
        #pragma unroll
        for (int rr = 1; rr < 4; ++rr) {
            int rank = (j + rr) & 3;
            uint32_t hb = hbase[rank];
            for (int i = tid; i < 1024; i += 512) {
                int n = i >> 4, dl = i & 15;
                h_s[n * 68 + rank * 16 + dl] = ldc_f32(hb + (uint32_t)(n * 17 + dl) * 4);
            }
        }
    }
    CLUSTER_SYNC();   // no CTA exits while peers may still read its DSMEM
}

// ---------------------------------------------------------------------------
// Final projection + node max-pool
// ---------------------------------------------------------------------------
__global__ void final_kernel(const float* __restrict__ Wp, const float* __restrict__ bp,
                             float* __restrict__ out)
{
    __shared__ float red[64 * 4];
    const int b = blockIdx.x, n = threadIdx.x;
    const float* h = d_last + (size_t)b * 4096 + n * 64;
    float l0 = bp[0], l1 = bp[1], l2 = bp[2], l3 = bp[3];
    #pragma unroll 8
    for (int d = 0; d < 64; ++d) {
        float v = fmaxf(h[d], 0.f);
        l0 += v * Wp[d * 4 + 0];
        l1 += v * Wp[d * 4 + 1];
        l2 += v * Wp[d * 4 + 2];
        l3 += v * Wp[d * 4 + 3];
    }
    red[n * 4 + 0] = l0; red[n * 4 + 1] = l1; red[n * 4 + 2] = l2; red[n * 4 + 3] = l3;
    __syncthreads();
    for (int s = 32; s > 0; s >>= 1) {
        if (n < s) {
            #pragma unroll
            for (int c = 0; c < 4; ++c)
                red[n * 4 + c] = fmaxf(red[n * 4 + c], red[(n + s) * 4 + c]);
        }
        __syncthreads();
    }
    if (n < 4) out[b * 4 + n] = red[n];
}

// ---------------------------------------------------------------------------
extern "C" void kernel_launch(void* const* d_in, const int* in_sizes, int n_in,
                              void* d_out, int out_size)
{
    (void)in_sizes; (void)n_in; (void)out_size;
    const float* X   = (const float*)d_in[0];
    const int*   len = (const int*)  d_in[1];
    const float* S0  = (const float*)d_in[2];
    const float* S1  = (const float*)d_in[3];
    const float* Wg0 = (const float*)d_in[4];
    const float* bg0 = (const float*)d_in[5];
    const float* Wc0 = (const float*)d_in[6];
    const float* bc0 = (const float*)d_in[7];
    const float* Wg1 = (const float*)d_in[8];
    const float* bg1 = (const float*)d_in[9];
    const float* Wc1 = (const float*)d_in[10];
    const float* bc1 = (const float*)d_in[11];
    const float* Wp  = (const float*)d_in[12];
    const float* bp  = (const float*)d_in[13];
    float* out = (float*)d_out;

    cudaFuncSetAttribute(pre_kernel,  cudaFuncAttributeMaxDynamicSharedMemorySize, PRE_SMEM_BYTES);
    cudaFuncSetAttribute(scan_kernel, cudaFuncAttributeMaxDynamicSharedMemorySize, SCAN_SMEM_BYTES);

    prep_kernel<<<2, 256>>>(S0, S1);
    pre_kernel<<<B_ * T_, 512, PRE_SMEM_BYTES>>>(X, Wg0, bg0, Wc0, bc0, 0);
    scan_kernel<<<128, 512, SCAN_SMEM_BYTES>>>(Wg0, Wc0, len, 0);
    pre_kernel<<<B_ * T_, 512, PRE_SMEM_BYTES>>>(X, Wg1, bg1, Wc1, bc1, 1);
    scan_kernel<<<128, 512, SCAN_SMEM_BYTES>>>(Wg1, Wc1, len, 1);
    final_kernel<<<B_, 64>>>(Wp, bp, out);
}

// round 10
// speedup vs baseline: 1.3174x; 1.0027x over previous
#include <cuda_runtime.h>
#include <math.h>
#include <stdint.h>

#define B_ 32
#define T_ 128

typedef unsigned long long u64t;

// Scratch (device globals: allocation-free)
__device__ float d_M[4 * 4096];                 // S0, 2S0^2-I, S1, 2S1^2-I
__device__ float d_out0[B_ * T_ * 4096];        // layer-0 h states
__device__ float d_last[B_ * 4096];             // layer-1 h at last relevant t
__device__ float d_Gx[(size_t)B_ * T_ * 64 * 128]; // gate x-part preactivations (+bias)
__device__ float d_Cx[(size_t)B_ * T_ * 64 * 64];  // cand x-part preactivations (+bias)

// ---------------- f32x2 helpers ----------------
__device__ __forceinline__ u64t pack_dup(float x) {
    u64t r; asm("mov.b64 %0, {%1,%1};" : "=l"(r) : "f"(x)); return r;
}
__device__ __forceinline__ u64t pack2(float lo, float hi) {
    u64t r; asm("mov.b64 %0, {%1,%2};" : "=l"(r) : "f"(lo), "f"(hi)); return r;
}
__device__ __forceinline__ float2 unpack2(u64t v) {
    float2 f; asm("mov.b64 {%0,%1}, %2;" : "=f"(f.x), "=f"(f.y) : "l"(v)); return f;
}
__device__ __forceinline__ void fma2(u64t& d, u64t a, u64t b) {
    asm("fma.rn.f32x2 %0, %1, %2, %0;" : "+l"(d) : "l"(a), "l"(b));
}

__device__ __forceinline__ uint32_t s_u32(const void* p) {
    return (uint32_t)__cvta_generic_to_shared(p);
}
__device__ __forceinline__ uint32_t mapa_rank(uint32_t a, uint32_t r) {
    uint32_t o;
    asm("mapa.shared::cluster.u32 %0, %1, %2;" : "=r"(o) : "r"(a), "r"(r));
    return o;
}
__device__ __forceinline__ float ldc_f32(uint32_t a) {
    float v;
    asm volatile("ld.shared::cluster.f32 %0, [%1];" : "=f"(v) : "r"(a));
    return v;
}
__device__ __forceinline__ void cp16(float* dst, const float* src) {
    asm volatile("cp.async.cg.shared.global [%0], [%1], 16;"
                 :: "r"(s_u32(dst)), "l"(src));
}
#define CP_COMMIT() asm volatile("cp.async.commit_group;")
#define CP_WAIT1()  asm volatile("cp.async.wait_group 1;")
#define CLUSTER_ARRIVE() asm volatile("barrier.cluster.arrive.aligned;" ::: "memory")
#define CLUSTER_WAIT()   asm volatile("barrier.cluster.wait.aligned;"   ::: "memory")
#define CLUSTER_SYNC() do { CLUSTER_ARRIVE(); CLUSTER_WAIT(); } while (0)

// fast activations (bounded preactivations; __expf/__fdividef err ~1e-6 rel)
__device__ __forceinline__ float sigmoid_f(float v) {
    return __fdividef(1.f, 1.f + __expf(-v));
}
__device__ __forceinline__ float tanh_f(float v) {
    return 1.f - __fdividef(2.f, __expf(2.f * v) + 1.f);
}

extern __shared__ float smem[];

// ---------------------------------------------------------------------------
// Precompute diffusion operators.
// ---------------------------------------------------------------------------
__global__ void prep_kernel(const float* __restrict__ S0, const float* __restrict__ S1)
{
    __shared__ float Ss[64 * 64];
    const int s = blockIdx.x;
    const float* S = s ? S1 : S0;
    for (int i = threadIdx.x; i < 4096; i += blockDim.x) Ss[i] = S[i];
    __syncthreads();
    for (int i = threadIdx.x; i < 4096; i += blockDim.x) {
        int m = i >> 6, n = i & 63;
        float acc = 0.f;
        #pragma unroll 8
        for (int p = 0; p < 64; ++p) acc += Ss[m * 64 + p] * Ss[p * 64 + n];
        d_M[(2 * s) * 4096 + i]     = Ss[i];
        d_M[(2 * s + 1) * 4096 + i] = 2.f * acc - (m == n ? 1.f : 0.f);
    }
}

// ---------------------------------------------------------------------------
// Precompute x-contributions for every (b,t). (R8 version, unchanged)
// ---------------------------------------------------------------------------
#define PRE_SMEM_FLOATS 50048
#define PRE_SMEM_BYTES (PRE_SMEM_FLOATS * 4)

__global__ void __launch_bounds__(512, 1)
pre_kernel(const float* __restrict__ Xin,
           const float* __restrict__ Wg, const float* __restrict__ bg,
           const float* __restrict__ Wc, const float* __restrict__ bc,
           int layer)
{
    float* x_row = smem;             // [node][feat] pitch 68 (uniform vec reads)
    float* x_T   = smem + 4352;      // [feat][node] pitch 66
    float* xa_T  = smem + 8576;      // 4 x [feat][node] pitch 66
    float* M_T   = smem + 25472;     // phase1: 4 x [in][out] pitch 66
    float* wbuf  = smem + 25472;     // phase2: 2 x 12288 (gate[p][128], cand @8192 [p][64])

    const int tid  = threadIdx.x;
    const int bt   = blockIdx.x;
    const int lane = tid & 31;
    const int g    = tid >> 5;           // warp 0..15

    const float* xsrc = (layer ? d_out0 : Xin) + (size_t)bt * 4096;

    for (int i = tid; i < 4096; i += 512) {
        int n = i >> 6, d = i & 63;
        float v = xsrc[i];
        x_row[n * 68 + d] = v;
        x_T[d * 66 + n]   = v;
    }
    for (int i = tid; i < 16384; i += 512) {
        int k = i >> 12, r = (i >> 6) & 63, c = i & 63;   // d_M[k][out=r][in=c]
        M_T[k * 4224 + c * 66 + r] = d_M[i];
    }
    __syncthreads();

    // ---------------- phase 1: xa_k = M_k @ x (stored transposed) ----------------
    {
        const int c4 = g * 4;
        #pragma unroll
        for (int k = 0; k < 4; ++k) {
            const float* MT = M_T + k * 4224;
            u64t a00 = 0, a01 = 0, a10 = 0, a11 = 0;
            #pragma unroll 4
            for (int p = 0; p < 64; ++p) {
                u64t d0 = pack_dup(MT[p * 66 + lane]);
                u64t d1 = pack_dup(MT[p * 66 + lane + 32]);
                ulonglong2 xv = *(const ulonglong2*)(x_row + p * 68 + c4); // uniform
                fma2(a00, d0, xv.x); fma2(a01, d0, xv.y);
                fma2(a10, d1, xv.x); fma2(a11, d1, xv.y);
            }
            float* XT = xa_T + k * 4224;
            float2 v00 = unpack2(a00), v01 = unpack2(a01);
            float2 v10 = unpack2(a10), v11 = unpack2(a11);
            XT[(c4 + 0) * 66 + lane] = v00.x;
            XT[(c4 + 1) * 66 + lane] = v00.y;
            XT[(c4 + 2) * 66 + lane] = v01.x;
            XT[(c4 + 3) * 66 + lane] = v01.y;
            XT[(c4 + 0) * 66 + lane + 32] = v10.x;
            XT[(c4 + 1) * 66 + lane + 32] = v10.y;
            XT[(c4 + 2) * 66 + lane + 32] = v11.x;
            XT[(c4 + 3) * 66 + lane + 32] = v11.y;
        }
    }
    __syncthreads();   // M_T reads done -> wbuf may overwrite

    // ---------------- phase 2: Gx / Cx with cp.async'd W ----------------
    const int gb = g * 8;
    const int cb = g * 4;

    {
        float* wb = wbuf;
        for (int i = tid; i < 2048; i += 512) cp16(wb + i * 4, Wg + i * 4);
        for (int i = tid; i < 1024; i += 512) cp16(wb + 8192 + i * 4, Wc + i * 4);
        CP_COMMIT();
    }

    u64t ag0[4], ag1[4], ac0[2], ac1[2];
    #pragma unroll
    for (int q = 0; q < 4; ++q) {
        u64t bb = pack2(bg[gb + 2 * q], bg[gb + 2 * q + 1]);
        ag0[q] = bb; ag1[q] = bb;
    }
    #pragma unroll
    for (int q = 0; q < 2; ++q) {
        u64t bb = pack2(bc[cb + 2 * q], bc[cb + 2 * q + 1]);
        ac0[q] = bb; ac1[q] = bb;
    }

    #pragma unroll
    for (int k = 0; k < 5; ++k) {
        if (k < 4) {
            float* wb = wbuf + ((k + 1) & 1) * 12288;
            const float* wgk = Wg + (size_t)((k + 1) * 128) * 128;
            const float* wck = Wc + (size_t)((k + 1) * 128) * 64;
            for (int i = tid; i < 2048; i += 512) cp16(wb + i * 4, wgk + i * 4);
            for (int i = tid; i < 1024; i += 512) cp16(wb + 8192 + i * 4, wck + i * 4);
        }
        CP_COMMIT();
        CP_WAIT1();
        __syncthreads();

        const float* AT  = (k == 0) ? x_T : (xa_T + (k - 1) * 4224);
        const float* wgb = wbuf + (k & 1) * 12288 + gb;
        const float* wcb = wbuf + (k & 1) * 12288 + 8192 + cb;

        #pragma unroll 4
        for (int p = 0; p < 64; ++p) {
            u64t a0 = pack_dup(AT[p * 66 + lane]);
            u64t a1 = pack_dup(AT[p * 66 + lane + 32]);
            ulonglong2 w0 = *(const ulonglong2*)(wgb + p * 128);
            ulonglong2 w1 = *(const ulonglong2*)(wgb + p * 128 + 4);
            ulonglong2 wc = *(const ulonglong2*)(wcb + p * 64);
            fma2(ag0[0], a0, w0.x); fma2(ag0[1], a0, w0.y);
            fma2(ag0[2], a0, w1.x); fma2(ag0[3], a0, w1.y);
            fma2(ag1[0], a1, w0.x); fma2(ag1[1], a1, w0.y);
            fma2(ag1[2], a1, w1.x); fma2(ag1[3], a1, w1.y);
            fma2(ac0[0], a0, wc.x); fma2(ac0[1], a0, wc.y);
            fma2(ac1[0], a1, wc.x); fma2(ac1[1], a1, wc.y);
        }
        __syncthreads();
    }

    float* gx = d_Gx + (size_t)bt * 8192;
    float* cx = d_Cx + (size_t)bt * 4096;
    ulonglong2 s;
    s.x = ag0[0]; s.y = ag0[1]; *(ulonglong2*)(gx + lane * 128 + gb)          = s;
    s.x = ag0[2]; s.y = ag0[3]; *(ulonglong2*)(gx + lane * 128 + gb + 4)      = s;
    s.x = ag1[0]; s.y = ag1[1]; *(ulonglong2*)(gx + (lane + 32) * 128 + gb)     = s;
    s.x = ag1[2]; s.y = ag1[3]; *(ulonglong2*)(gx + (lane + 32) * 128 + gb + 4) = s;
    s.x = ac0[0]; s.y = ac0[1]; *(ulonglong2*)(cx + lane * 64 + cb)           = s;
    s.x = ac1[0]; s.y = ac1[1]; *(ulonglong2*)(cx + (lane + 32) * 64 + cb)      = s;
}

// ---------------------------------------------------------------------------
// Persistent per-layer scan. Grid 128 = 32 batches x cluster(4).
// v6: 512 threads. V-phases split by INNER dim d (each half 32 d's) -> per-SMSP
// LDS and fma2 totals identical to the 256-thread version, warps doubled.
// Half-0 stores V, half-1 RMW-adds its partial. M-apply split by k
// (half0: base+k1,k2; half1: k3,k4) with 8-float partial exchange through the
// dead rh_s window. Smem layout identical to R8.
// ---------------------------------------------------------------------------
#define SCAN_SMEM_BYTES (56256 * 4)

__global__ void __launch_bounds__(512, 1) __cluster_dims__(4, 1, 1)
scan_kernel(const float* __restrict__ Wg, const float* __restrict__ Wc,
            const int* __restrict__ lens, int layer)
{
    float* wg_h = smem;
    float* wc_h = smem + 10240;
    float* Ms   = smem + 15360;
    float* h_s  = smem + 32768;   // pitch 68
    float* rh_s = smem + 37120;   // pitch 68; also yP partial overlay
    float* V_s  = smem + 41472;   // 5 x 64 x 36
    float* rst  = smem + 52992;
    float* ugs  = smem + 54080;
    float* hst  = smem + 55168;
    float* yP   = rh_s;           // partial-y overlay (rh dead in those windows)

    const int tid = threadIdx.x;
    const int b = blockIdx.x >> 2;
    const int j = blockIdx.x & 3;

    // one-time loads
    for (int i = tid; i < 10240; i += 512) {
        int k = i >> 11, d = (i >> 5) & 63, c = i & 31;
        int g = (c < 16) ? (j * 16 + c) : (64 + j * 16 + (c - 16));
        wg_h[i] = Wg[(size_t)(k * 128 + 64 + d) * 128 + g];
    }
    for (int i = tid; i < 5120; i += 512) {
        int k = i >> 10, d = (i >> 4) & 63, c = i & 15;
        wc_h[i] = Wc[(size_t)(k * 128 + 64 + d) * 64 + j * 16 + c];
    }
    for (int i = tid; i < 16384; i += 512) {
        int k = i >> 12, r = (i >> 6) & 63, p = i & 63;
        Ms[k * 4352 + r * 68 + p] = d_M[i];
    }
    for (int i = tid; i < 4096; i += 512)
        h_s[(i >> 6) * 68 + (i & 63)] = 0.f;

    int idx_t = lens[b] - 1;
    idx_t = idx_t < 0 ? 0 : (idx_t > T_ - 1 ? T_ - 1 : idx_t);

    uint32_t rbase[4], hbase[4];
    #pragma unroll
    for (int r = 0; r < 4; ++r) {
        rbase[r] = mapa_rank(s_u32(rst), (uint32_t)r);
        hbase[r] = mapa_rank(s_u32(hst), (uint32_t)r);
    }

    const int rg  = tid & 31;            // V-phase row
    const int jg  = (tid >> 5) & 7;      // V-phase col group
    const int dh  = tid >> 8;            // inner-dim half / k-half
    const int s5  = tid & 255;           // M-apply sub-id
    const int mg  = s5 >> 3;             // M-apply row (0..31), rows {mg, mg+32}
    const int ja4 = (s5 & 7) * 4;
    const int ja2 = (s5 & 7) * 2;
    const int g0  = (ja4 < 16) ? (j * 16 + ja4) : (64 + j * 16 + (ja4 - 16));
    const int c0  = j * 16 + ja2;
    const u64t ONE = pack_dup(1.f);

    const float* gxb = d_Gx + (size_t)b * T_ * 8192;
    const float* cxb = d_Cx + (size_t)b * T_ * 4096;

    for (int t = 0; t < T_; ++t) {
        __syncthreads();

        float4 gA = make_float4(0.f, 0.f, 0.f, 0.f);
        float4 gB = gA;
        float2 cA = make_float2(0.f, 0.f);
        float2 cB = cA;
        if (dh == 0) {
            const float* gx = gxb + (size_t)t * 8192;
            const float* cx = cxb + (size_t)t * 4096;
            gA = __ldg((const float4*)(gx + mg * 128 + g0));
            gB = __ldg((const float4*)(gx + (mg + 32) * 128 + g0));
            cA = __ldg((const float2*)(cx + mg * 64 + c0));
            cB = __ldg((const float2*)(cx + (mg + 32) * 64 + c0));
        }

        // ---------- gate V-phase (d-split) ----------
        {
            u64t acc[5][4];
            #pragma unroll
            for (int k = 0; k < 5; ++k) { acc[k][0] = acc[k][1] = acc[k][2] = acc[k][3] = 0; }
            const float* h0p = h_s + rg * 68 + dh * 32;
            const float* h1p = h_s + (rg + 32) * 68 + dh * 32;
            const float* wbase = wg_h + jg * 4 + dh * 1024;   // (dh*32 + d) * 32
            #pragma unroll 2
            for (int d4 = 0; d4 < 32; d4 += 4) {
                float4 hv0 = *(const float4*)(h0p + d4);
                float4 hv1 = *(const float4*)(h1p + d4);
                float h0a[4] = {hv0.x, hv0.y, hv0.z, hv0.w};
                float h1a[4] = {hv1.x, hv1.y, hv1.z, hv1.w};
                #pragma unroll
                for (int q = 0; q < 4; ++q) {
                    u64t a0 = pack_dup(h0a[q]);
                    u64t a1 = pack_dup(h1a[q]);
                    #pragma unroll
                    for (int k = 0; k < 5; ++k) {
                        ulonglong2 w = *(const ulonglong2*)(wbase + k * 2048 + (d4 + q) * 32);
                        fma2(acc[k][0], a0, w.x); fma2(acc[k][1], a0, w.y);
                        fma2(acc[k][2], a1, w.x); fma2(acc[k][3], a1, w.y);
                    }
                }
            }
            if (dh == 0) {
                #pragma unroll
                for (int k = 0; k < 5; ++k) {
                    ulonglong2 sv;
                    sv.x = acc[k][0]; sv.y = acc[k][1];
                    *(ulonglong2*)(V_s + k * 2304 + rg * 36 + jg * 4) = sv;
                    sv.x = acc[k][2]; sv.y = acc[k][3];
                    *(ulonglong2*)(V_s + k * 2304 + (rg + 32) * 36 + jg * 4) = sv;
                }
            }
            __syncthreads();
            if (dh == 1) {
                #pragma unroll
                for (int k = 0; k < 5; ++k) {
                    float* p0 = V_s + k * 2304 + rg * 36 + jg * 4;
                    float* p1 = V_s + k * 2304 + (rg + 32) * 36 + jg * 4;
                    ulonglong2 c0v = *(ulonglong2*)p0;
                    ulonglong2 c1v = *(ulonglong2*)p1;
                    fma2(c0v.x, ONE, acc[k][0]); fma2(c0v.y, ONE, acc[k][1]);
                    fma2(c1v.x, ONE, acc[k][2]); fma2(c1v.y, ONE, acc[k][3]);
                    *(ulonglong2*)p0 = c0v;
                    *(ulonglong2*)p1 = c1v;
                }
            }
            __syncthreads();
        }

        // ---------- gate M-apply (k-split) + sigmoid + stage ----------
        {
            u64t y00, y01, y10, y11;
            if (dh == 0) {
                float4 vA = *(const float4*)(V_s + mg * 36 + ja4);
                float4 vB = *(const float4*)(V_s + (mg + 32) * 36 + ja4);
                y00 = pack2(gA.x + vA.x, gA.y + vA.y);
                y01 = pack2(gA.z + vA.z, gA.w + vA.w);
                y10 = pack2(gB.x + vB.x, gB.y + vB.y);
                y11 = pack2(gB.z + vB.z, gB.w + vB.w);
            } else {
                y00 = y01 = y10 = y11 = pack_dup(0.f);
            }
            const int kb = 1 + dh * 2;     // 1 or 3
            #pragma unroll
            for (int kk = 0; kk < 2; ++kk) {
                const float* Mk = Ms + (kb - 1 + kk) * 4352;
                const float* Vk = V_s + (kb + kk) * 2304;
                #pragma unroll 4
                for (int m = 0; m < 64; m += 4) {
                    float4 mA = *(const float4*)(Mk + mg * 68 + m);
                    float4 mB = *(const float4*)(Mk + (mg + 32) * 68 + m);
                    float mAa[4] = {mA.x, mA.y, mA.z, mA.w};
                    float mBa[4] = {mB.x, mB.y, mB.z, mB.w};
                    #pragma unroll
                    for (int q = 0; q < 4; ++q) {
                        ulonglong2 v = *(const ulonglong2*)(Vk + (m + q) * 36 + ja4);
                        u64t da = pack_dup(mAa[q]);
                        u64t db = pack_dup(mBa[q]);
                        fma2(y00, da, v.x); fma2(y01, da, v.y);
                        fma2(y10, db, v.x); fma2(y11, db, v.y);
                    }
                }
            }
            if (dh == 1) {
                ulonglong2 sv;
                sv.x = y00; sv.y = y01; *(ulonglong2*)(yP + s5 * 8)     = sv;
                sv.x = y10; sv.y = y11; *(ulonglong2*)(yP + s5 * 8 + 4) = sv;
            }
            __syncthreads();
            if (dh == 0) {
                ulonglong2 pa = *(const ulonglong2*)(yP + s5 * 8);
                ulonglong2 pb = *(const ulonglong2*)(yP + s5 * 8 + 4);
                fma2(y00, ONE, pa.x); fma2(y01, ONE, pa.y);
                fma2(y10, ONE, pb.x); fma2(y11, ONE, pb.y);
                float2 p00 = unpack2(y00), p01 = unpack2(y01);
                float2 p10 = unpack2(y10), p11 = unpack2(y11);
                float v0a[4] = {p00.x, p00.y, p01.x, p01.y};
                float v1a[4] = {p10.x, p10.y, p11.x, p11.y};
                #pragma unroll
                for (int q = 0; q < 4; ++q) {
                    int c = ja4 + q;
                    float s0 = sigmoid_f(v0a[q]);
                    float s1 = sigmoid_f(v1a[q]);
                    if (c < 16) { rst[mg * 17 + c] = s0;        rst[(mg + 32) * 17 + c] = s1; }
                    else        { ugs[mg * 17 + c - 16] = s0;   ugs[(mg + 32) * 17 + c - 16] = s1; }
                }
            }
            __syncthreads();
        }

        // r exchange: arrive, local quarter, wait, gather remote
        CLUSTER_ARRIVE();
        for (int i = tid; i < 1024; i += 512) {
            int n = i >> 4, dl = i & 15, d = j * 16 + dl;
            rh_s[n * 68 + d] = rst[n * 17 + dl] * h_s[n * 68 + d];
        }
        CLUSTER_WAIT();
        #pragma unroll
        for (int rr = 1; rr < 4; ++rr) {
            int rank = (j + rr) & 3;
            uint32_t rb = rbase[rank];
            for (int i = tid; i < 1024; i += 512) {
                int n = i >> 4, dl = i & 15, d = rank * 16 + dl;
                float r = ldc_f32(rb + (uint32_t)(n * 17 + dl) * 4);
                rh_s[n * 68 + d] = r * h_s[n * 68 + d];
            }
        }
        __syncthreads();

        // ---------- cand V-phase (d-split) ----------
        {
            u64t acc[5][2];
            #pragma unroll
            for (int k = 0; k < 5; ++k) { acc[k][0] = acc[k][1] = 0; }
            const float* h0p = rh_s + rg * 68 + dh * 32;
            const float* h1p = rh_s + (rg + 32) * 68 + dh * 32;
            const float* wbase = wc_h + jg * 2 + dh * 512;    // (dh*32 + d) * 16
            #pragma unroll 2
            for (int d4 = 0; d4 < 32; d4 += 4) {
                float4 hv0 = *(const float4*)(h0p + d4);
                float4 hv1 = *(const float4*)(h1p + d4);
                float h0a[4] = {hv0.x, hv0.y, hv0.z, hv0.w};
                float h1a[4] = {hv1.x, hv1.y, hv1.z, hv1.w};
                #pragma unroll
                for (int q = 0; q < 4; ++q) {
                    u64t a0 = pack_dup(h0a[q]);
                    u64t a1 = pack_dup(h1a[q]);
                    #pragma unroll
                    for (int k = 0; k < 5; ++k) {
                        u64t w = *(const u64t*)(wbase + k * 1024 + (d4 + q) * 16);
                        fma2(acc[k][0], a0, w);
                        fma2(acc[k][1], a1, w);
                    }
                }
            }
            if (dh == 0) {
                #pragma unroll
                for (int k = 0; k < 5; ++k) {
                    *(u64t*)(V_s + k * 2304 + rg * 36 + jg * 2)        = acc[k][0];
                    *(u64t*)(V_s + k * 2304 + (rg + 32) * 36 + jg * 2) = acc[k][1];
                }
            }
            __syncthreads();
            if (dh == 1) {
                #pragma unroll
                for (int k = 0; k < 5; ++k) {
                    float* p0 = V_s + k * 2304 + rg * 36 + jg * 2;
                    float* p1 = V_s + k * 2304 + (rg + 32) * 36 + jg * 2;
                    u64t c0v = *(u64t*)p0;
                    u64t c1v = *(u64t*)p1;
                    fma2(c0v, ONE, acc[k][0]);
                    fma2(c1v, ONE, acc[k][1]);
                    *(u64t*)p0 = c0v;
                    *(u64t*)p1 = c1v;
                }
            }
            __syncthreads();
        }

        // ---------- cand M-apply (k-split) + GRU update ----------
        {
            u64t y0, y1;
            if (dh == 0) {
                float2 v0 = *(const float2*)(V_s + mg * 36 + ja2);
                float2 v1 = *(const float2*)(V_s + (mg + 32) * 36 + ja2);
                y0 = pack2(cA.x + v0.x, cA.y + v0.y);
                y1 = pack2(cB.x + v1.x, cB.y + v1.y);
            } else {
                y0 = y1 = pack_dup(0.f);
            }
            const int kb = 1 + dh * 2;
            #pragma unroll
            for (int kk = 0; kk < 2; ++kk) {
                const float* Mk = Ms + (kb - 1 + kk) * 4352;
                const float* Vk = V_s + (kb + kk) * 2304;
                #pragma unroll 4
                for (int m = 0; m < 64; m += 4) {
                    float4 mA = *(const float4*)(Mk + mg * 68 + m);
                    float4 mB = *(const float4*)(Mk + (mg + 32) * 68 + m);
                    float mAa[4] = {mA.x, mA.y, mA.z, mA.w};
                    float mBa[4] = {mB.x, mB.y, mB.z, mB.w};
                    #pragma unroll
                    for (int q = 0; q < 4; ++q) {
                        u64t v = *(const u64t*)(Vk + (m + q) * 36 + ja2);
                        fma2(y0, pack_dup(mAa[q]), v);
                        fma2(y1, pack_dup(mBa[q]), v);
                    }
                }
            }
            if (dh == 1) {
                *(u64t*)(yP + s5 * 4)     = y0;
                *(u64t*)(yP + s5 * 4 + 2) = y1;
            }
            __syncthreads();
            if (dh == 0) {
                u64t pa = *(const u64t*)(yP + s5 * 4);
                u64t pb = *(const u64t*)(yP + s5 * 4 + 2);
                fma2(y0, ONE, pa);
                fma2(y1, ONE, pb);
                float* hout0 = d_out0 + ((size_t)(b * T_ + t)) * 4096;
                float2 cc0 = unpack2(y0), cc1 = unpack2(y1);
                float cand0[2] = {cc0.x, cc0.y};
                float cand1[2] = {cc1.x, cc1.y};
                #pragma unroll
                for (int q = 0; q < 2; ++q) {
                    int cl = ja2 + q;
                    int col = j * 16 + cl;
                    float cv0 = tanh_f(cand0[q]);
                    float ug0 = ugs[mg * 17 + cl];
                    float hn0 = ug0 * h_s[mg * 68 + col] + (1.f - ug0) * cv0;
                    hst[mg * 17 + cl] = hn0;
                    float cv1 = tanh_f(cand1[q]);
                    float ug1 = ugs[(mg + 32) * 17 + cl];
                    float hn1 = ug1 * h_s[(mg + 32) * 68 + col] + (1.f - ug1) * cv1;
                    hst[(mg + 32) * 17 + cl] = hn1;
                    if (layer == 0) {
                        hout0[mg * 64 + col]        = hn0;
                        hout0[(mg + 32) * 64 + col] = hn1;
                    } else if (t == idx_t) {
                        d_last[(size_t)b * 4096 + mg * 64 + col]        = hn0;
                        d_last[(size_t)b * 4096 + (mg + 32) * 64 + col] = hn1;
                    }
                }
            }
            __syncthreads();
        }

        // h exchange: arrive, local quarter, wait, gather remote
        CLUSTER_ARRIVE();
        for (int i = tid; i < 1024; i += 512) {
            int n = i >> 4, dl = i & 15;
            h_s[n * 68 + j * 16 + dl] = hst[n * 17 + dl];
        }
        CLUSTER_WAIT();
        #pragma unroll
        for (int rr = 1; rr < 4; ++rr) {
            int rank = (j + rr) & 3;
            uint32_t hb = hbase[rank];
            for (int i = tid; i < 1024; i += 512) {
                int n = i >> 4, dl = i & 15;
                h_s[n * 68 + rank * 16 + dl] = ldc_f32(hb + (uint32_t)(n * 17 + dl) * 4);
            }
        }
    }
    CLUSTER_SYNC();   // no CTA exits while peers may still read its DSMEM
}

// ---------------------------------------------------------------------------
// Final projection + node max-pool
// ---------------------------------------------------------------------------
__global__ void final_kernel(const float* __restrict__ Wp, const float* __restrict__ bp,
                             float* __restrict__ out)
{
    __shared__ float red[64 * 4];
    const int b = blockIdx.x, n = threadIdx.x;
    const float* h = d_last + (size_t)b * 4096 + n * 64;
    float l0 = bp[0], l1 = bp[1], l2 = bp[2], l3 = bp[3];
    #pragma unroll 8
    for (int d = 0; d < 64; ++d) {
        float v = fmaxf(h[d], 0.f);
        l0 += v * Wp[d * 4 + 0];
        l1 += v * Wp[d * 4 + 1];
        l2 += v * Wp[d * 4 + 2];
        l3 += v * Wp[d * 4 + 3];
    }
    red[n * 4 + 0] = l0; red[n * 4 + 1] = l1; red[n * 4 + 2] = l2; red[n * 4 + 3] = l3;
    __syncthreads();
    for (int s = 32; s > 0; s >>= 1) {
        if (n < s) {
            #pragma unroll
            for (int c = 0; c < 4; ++c)
                red[n * 4 + c] = fmaxf(red[n * 4 + c], red[(n + s) * 4 + c]);
        }
        __syncthreads();
    }
    if (n < 4) out[b * 4 + n] = red[n];
}

// ---------------------------------------------------------------------------
extern "C" void kernel_launch(void* const* d_in, const int* in_sizes, int n_in,
                              void* d_out, int out_size)
{
    (void)in_sizes; (void)n_in; (void)out_size;
    const float* X   = (const float*)d_in[0];
    const int*   len = (const int*)  d_in[1];
    const float* S0  = (const float*)d_in[2];
    const float* S1  = (const float*)d_in[3];
    const float* Wg0 = (const float*)d_in[4];
    const float* bg0 = (const float*)d_in[5];
    const float* Wc0 = (const float*)d_in[6];
    const float* bc0 = (const float*)d_in[7];
    const float* Wg1 = (const float*)d_in[8];
    const float* bg1 = (const float*)d_in[9];
    const float* Wc1 = (const float*)d_in[10];
    const float* bc1 = (const float*)d_in[11];
    const float* Wp  = (const float*)d_in[12];
    const float* bp  = (const float*)d_in[13];
    float* out = (float*)d_out;

    cudaFuncSetAttribute(pre_kernel,  cudaFuncAttributeMaxDynamicSharedMemorySize, PRE_SMEM_BYTES);
    cudaFuncSetAttribute(scan_kernel, cudaFuncAttributeMaxDynamicSharedMemorySize, SCAN_SMEM_BYTES);

    prep_kernel<<<2, 256>>>(S0, S1);
    pre_kernel<<<B_ * T_, 512, PRE_SMEM_BYTES>>>(X, Wg0, bg0, Wc0, bc0, 0);
    scan_kernel<<<128, 512, SCAN_SMEM_BYTES>>>(Wg0, Wc0, len, 0);
    pre_kernel<<<B_ * T_, 512, PRE_SMEM_BYTES>>>(X, Wg1, bg1, Wc1, bc1, 1);
    scan_kernel<<<128, 512, SCAN_SMEM_BYTES>>>(Wg1, Wc1, len, 1);
    final_kernel<<<B_, 64>>>(Wp, bp, out);
}